// round 1
// baseline (speedup 1.0000x reference)
#include <cuda_runtime.h>

// Problem constants
#define BATCH   8192
#define IN_CH   64
#define BOARD   27
#define ROWS    49
#define CH      256
#define XCOLS   (IN_CH * BOARD)   // 1728
#define OUTCOLS (ROWS * CH)       // 12544
#define KTOT    (3 * IN_CH)       // 192 effective K per row-group

// GEMM tiling
#define BM 128
#define BN 128
#define BK 16
#define TM 8
#define TN 8
#define NTHREADS 256

// cell[r][e] = board cell index of the e-th stone of win-line r
__device__ int d_cell[ROWS * 3];

// Faithful port of init_wincon_matrix(): records which cell each (col, step)
// put() touches. Every line gets exactly 3 puts and step cycles 0,1,2 per line.
__global__ void init_cell_kernel() {
    if (threadIdx.x != 0 || blockIdx.x != 0) return;
    int col = 0, step = 0;
    int x, y, z;
#define PUT(X, Y, Z) do { d_cell[col * 3 + step] = (X) + 3 * (Y) + 9 * (Z); \
                          step = (step + 1) % 3; } while (0)
    for (x = 0; x < 3; x++) {
        for (y = 0; y < 3; y++) { for (z = 0; z < 3; z++) PUT(x, y, z); col++; }
        for (z = 0; z < 3; z++) { for (y = 0; y < 3; y++) PUT(x, y, z); col++; }
        for (y = 0; y < 3; y++) { z = y;     PUT(x, y, z); } col++;
        for (y = 0; y < 3; y++) { z = 2 - y; PUT(x, y, z); } col++;
    }
    for (z = 0; z < 3; z++) {
        for (y = 0; y < 3; y++) { for (x = 0; x < 3; x++) PUT(x, y, z); col++; }
        for (y = 0; y < 3; y++) { x = y;     PUT(x, y, z); } col++;
        for (y = 0; y < 3; y++) { x = 2 - y; PUT(x, y, z); } col++;
    }
    for (y = 0; y < 3; y++) {
        for (z = 0; z < 3; z++) { x = z;     PUT(x, y, z); } col++;
        for (z = 0; z < 3; z++) { x = 2 - z; PUT(x, y, z); } col++;
    }
    for (x = 0; x < 3; x++) { y = x;     z = x;     PUT(x, y, z); } col++;
    for (x = 0; x < 3; x++) { y = 2 - x; z = 2 - x; PUT(x, y, z); } col++;
    for (x = 0; x < 3; x++) { y = x;     z = 2 - x; PUT(x, y, z); } col++;
    for (x = 0; x < 3; x++) { z = x;     y = 2 - x; PUT(x, y, z); } col++;
#undef PUT
}

// Per (batch-tile bt, line r, col-tile ct):
//   C[128,128] = A[128,192] * B[192,128] + bias
// A gathers x columns cell[r][e]*64 + i ; B = v[e,i,r, ct*128 + n]
__global__ __launch_bounds__(NTHREADS, 2)
void tic_gemm_kernel(const float* __restrict__ x,
                     const float* __restrict__ v,
                     const float* __restrict__ bias,
                     float* __restrict__ out)
{
    const int ct = blockIdx.x;   // 0..1   (column tile within the 256-wide row group)
    const int r  = blockIdx.y;   // 0..48  (win line)
    const int bt = blockIdx.z;   // 0..63  (batch tile)

    __shared__ float As[BK][BM];      // transposed A chunk
    __shared__ float Bs[BK][BN];

    const int tid = threadIdx.x;
    const int tm  = tid / 16;         // 0..15
    const int tn  = tid % 16;         // 0..15

    // A loaders: 128 rows x 16 cols; 4 threads/row (float4), 2 rows/thread
    const int a_row  = tid / 4;              // 0..63 (and +64)
    const int a_col4 = (tid % 4) * 4;        // 0,4,8,12
    // B loaders: 16 rows x 128 cols; 8 threads/row wait -> 32 threads/row? :
    // row = tid/32 (0..7, and +8), 32 threads cover 128 floats via float4
    const int b_row  = tid / 32;             // 0..7 (and +8)
    const int b_col4 = (tid % 32) * 4;       // 0..124

    const float* xb = x + (size_t)(bt * BM) * XCOLS;
    // v[e,i,r,c] at offset ((e*64+i)*49 + r)*256 + c = k*12544 + r*256 + c
    const float* vb = v + (size_t)r * CH + (size_t)ct * BN;

    const int c0 = d_cell[r * 3 + 0] * IN_CH;
    const int c1 = d_cell[r * 3 + 1] * IN_CH;
    const int c2 = d_cell[r * 3 + 2] * IN_CH;

    float acc[TM][TN];
#pragma unroll
    for (int i = 0; i < TM; i++)
#pragma unroll
        for (int j = 0; j < TN; j++) acc[i][j] = 0.0f;

#pragma unroll 1
    for (int kc = 0; kc < KTOT; kc += BK) {
        const int e = kc >> 6;                     // 64 % 16 == 0: chunk stays in one e-block
        const int cellbase = (e == 0 ? c0 : (e == 1 ? c1 : c2)) + (kc & 63);

        // --- load A chunk (gathered x columns), store transposed ---
#pragma unroll
        for (int s = 0; s < 2; s++) {
            const int m = a_row + s * 64;
            float4 t = *(const float4*)(xb + (size_t)m * XCOLS + cellbase + a_col4);
            As[a_col4 + 0][m] = t.x;
            As[a_col4 + 1][m] = t.y;
            As[a_col4 + 2][m] = t.z;
            As[a_col4 + 3][m] = t.w;
        }
        // --- load B chunk ---
#pragma unroll
        for (int s = 0; s < 2; s++) {
            const int k = b_row + s * 8;
            float4 t = *(const float4*)(vb + (size_t)(kc + k) * OUTCOLS + b_col4);
            *(float4*)&Bs[k][b_col4] = t;
        }
        __syncthreads();

#pragma unroll
        for (int k = 0; k < BK; k++) {
            float a[TM], b[TN];
            float4 a0 = *(const float4*)&As[k][tm * TM];
            float4 a1 = *(const float4*)&As[k][tm * TM + 4];
            float4 b0 = *(const float4*)&Bs[k][tn * TN];
            float4 b1 = *(const float4*)&Bs[k][tn * TN + 4];
            a[0]=a0.x; a[1]=a0.y; a[2]=a0.z; a[3]=a0.w;
            a[4]=a1.x; a[5]=a1.y; a[6]=a1.z; a[7]=a1.w;
            b[0]=b0.x; b[1]=b0.y; b[2]=b0.z; b[3]=b0.w;
            b[4]=b1.x; b[5]=b1.y; b[6]=b1.z; b[7]=b1.w;
#pragma unroll
            for (int i = 0; i < TM; i++)
#pragma unroll
                for (int j = 0; j < TN; j++)
                    acc[i][j] = fmaf(a[i], b[j], acc[i][j]);
        }
        __syncthreads();
    }

    // --- epilogue: add bias, vectorized stores ---
    const int outc = r * CH + ct * BN + tn * TN;
    float bsv[TN];
#pragma unroll
    for (int j = 0; j < TN; j++) bsv[j] = bias[outc + j];

#pragma unroll
    for (int i = 0; i < TM; i++) {
        const int m = bt * BM + tm * TM + i;
        float4 o0, o1;
        o0.x = acc[i][0] + bsv[0]; o0.y = acc[i][1] + bsv[1];
        o0.z = acc[i][2] + bsv[2]; o0.w = acc[i][3] + bsv[3];
        o1.x = acc[i][4] + bsv[4]; o1.y = acc[i][5] + bsv[5];
        o1.z = acc[i][6] + bsv[6]; o1.w = acc[i][7] + bsv[7];
        float* op = out + (size_t)m * OUTCOLS + outc;
        *(float4*)(op)     = o0;
        *(float4*)(op + 4) = o1;
    }
}

extern "C" void kernel_launch(void* const* d_in, const int* in_sizes, int n_in,
                              void* d_out, int out_size)
{
    // Identify inputs robustly by element count (metadata order is x, v, b,
    // but sizes are unambiguous anyway).
    const float* x = nullptr;    // 8192*1728  = 14155776
    const float* v = nullptr;    // 3*64*49*256 = 2408448
    const float* b = nullptr;    // 12544
    for (int i = 0; i < n_in; i++) {
        if (in_sizes[i] == BATCH * XCOLS)            x = (const float*)d_in[i];
        else if (in_sizes[i] == 3 * IN_CH * OUTCOLS) v = (const float*)d_in[i];
        else if (in_sizes[i] == OUTCOLS)             b = (const float*)d_in[i];
    }
    float* out = (float*)d_out;

    init_cell_kernel<<<1, 32>>>();

    dim3 grid(CH / BN, ROWS, BATCH / BM);   // (2, 49, 64)
    tic_gemm_kernel<<<grid, NTHREADS>>>(x, v, b, out);
}

// round 3
// speedup vs baseline: 2.7930x; 2.7930x over previous
#include <cuda_runtime.h>
#include <cstdint>

// ---------------- Problem constants ----------------
#define BATCH   8192
#define IN_CH   64
#define XCOLS   1728           // 27*64
#define OUTCOLS 12544          // 49*256
#define ROWS    49
#define CH      256
#define KTOT    192            // 3*64
#define CHUNKS  6
#define KC      32             // K per chunk
#define BM      128
#define BN      128
#define NTHREADS 256

// SMEM: rows padded to 36 floats (144B) -> conflict-free ldmatrix (144 % 128 = 16)
#define ROWSTRIDE 36
#define TILE_BYTES (128 * ROWSTRIDE * 4)       // 18432
#define BUF_STRIDE (2 * TILE_BYTES)            // A+B per stage
#define SMEM_TOTAL (2 * BUF_STRIDE)            // 73728

__device__ int   d_cell[ROWS * 3];
__device__ float d_xR[(size_t)BATCH * XCOLS];            // rna-rounded x (56.6MB)
__device__ float d_vT[(size_t)ROWS * CH * KTOT];         // rounded, [r][n][k] (9.6MB)

// ---------------- helpers ----------------
__device__ __forceinline__ uint32_t smem_u32(const void* p) {
    uint32_t a;
    asm("{ .reg .u64 t; cvta.to.shared.u64 t, %1; cvt.u32.u64 %0, t; }" : "=r"(a) : "l"(p));
    return a;
}
__device__ __forceinline__ uint32_t f2tf32(float f) {
    uint32_t r;
    asm("cvt.rna.tf32.f32 %0, %1;" : "=r"(r) : "f"(f));
    return r;
}
__device__ __forceinline__ void cp_async16(uint32_t dst, const void* src) {
    asm volatile("cp.async.cg.shared.global [%0], [%1], 16;"
                 :: "r"(dst), "l"(__cvta_generic_to_global(src)) : "memory");
}
#define CP_COMMIT() asm volatile("cp.async.commit_group;" ::: "memory")
#define CP_WAIT(n)  asm volatile("cp.async.wait_group %0;" :: "n"(n) : "memory")

__device__ __forceinline__ void ldmx4(uint32_t* r, uint32_t addr) {
    asm volatile("ldmatrix.sync.aligned.m8n8.x4.shared.b16 {%0,%1,%2,%3}, [%4];"
                 : "=r"(r[0]), "=r"(r[1]), "=r"(r[2]), "=r"(r[3]) : "r"(addr));
}
__device__ __forceinline__ void mma_tf32(float* c, const uint32_t* a, const uint32_t* b) {
    asm volatile(
        "mma.sync.aligned.m16n8k8.row.col.f32.tf32.tf32.f32 "
        "{%0,%1,%2,%3}, {%4,%5,%6,%7}, {%8,%9}, {%0,%1,%2,%3};"
        : "+f"(c[0]), "+f"(c[1]), "+f"(c[2]), "+f"(c[3])
        : "r"(a[0]), "r"(a[1]), "r"(a[2]), "r"(a[3]), "r"(b[0]), "r"(b[1]));
}

// ---------------- init: win-line cell table ----------------
__global__ void init_cell_kernel() {
    if (threadIdx.x != 0 || blockIdx.x != 0) return;
    int col = 0, step = 0, x, y, z;
#define PUT(X, Y, Z) do { d_cell[col*3 + step] = (X) + 3*(Y) + 9*(Z); \
                          step = (step + 1) % 3; } while (0)
    for (x = 0; x < 3; x++) {
        for (y = 0; y < 3; y++) { for (z = 0; z < 3; z++) PUT(x,y,z); col++; }
        for (z = 0; z < 3; z++) { for (y = 0; y < 3; y++) PUT(x,y,z); col++; }
        for (y = 0; y < 3; y++) { z = y;     PUT(x,y,z); } col++;
        for (y = 0; y < 3; y++) { z = 2 - y; PUT(x,y,z); } col++;
    }
    for (z = 0; z < 3; z++) {
        for (y = 0; y < 3; y++) { for (x = 0; x < 3; x++) PUT(x,y,z); col++; }
        for (y = 0; y < 3; y++) { x = y;     PUT(x,y,z); } col++;
        for (y = 0; y < 3; y++) { x = 2 - y; PUT(x,y,z); } col++;
    }
    for (y = 0; y < 3; y++) {
        for (z = 0; z < 3; z++) { x = z;     PUT(x,y,z); } col++;
        for (z = 0; z < 3; z++) { x = 2 - z; PUT(x,y,z); } col++;
    }
    for (x = 0; x < 3; x++) { y = x;     z = x;     PUT(x,y,z); } col++;
    for (x = 0; x < 3; x++) { y = 2 - x; z = 2 - x; PUT(x,y,z); } col++;
    for (x = 0; x < 3; x++) { y = x;     z = 2 - x; PUT(x,y,z); } col++;
    for (x = 0; x < 3; x++) { z = x;     y = 2 - x; PUT(x,y,z); } col++;
#undef PUT
}

// ---------------- pre-pass: rna-round x ----------------
__global__ void round_x_kernel(const float* __restrict__ x) {
    const size_t n4 = (size_t)BATCH * XCOLS / 4;
    const uint4* src = reinterpret_cast<const uint4*>(x);
    uint4* dst = reinterpret_cast<uint4*>(d_xR);
    for (size_t i = blockIdx.x * (size_t)blockDim.x + threadIdx.x;
         i < n4; i += (size_t)gridDim.x * blockDim.x) {
        uint4 t = src[i];
        t.x = f2tf32(__uint_as_float(t.x));
        t.y = f2tf32(__uint_as_float(t.y));
        t.z = f2tf32(__uint_as_float(t.z));
        t.w = f2tf32(__uint_as_float(t.w));
        dst[i] = t;
    }
}

// ---------------- pre-pass: transpose+round v -> [r][n][k] ----------------
__global__ void build_vT_kernel(const float* __restrict__ v) {
    const int r = blockIdx.x;
    const float* vb = v + (size_t)r * CH;
    float* dst = d_vT + (size_t)r * CH * KTOT;
    for (int u = threadIdx.x; u < CH * (KTOT / 4); u += blockDim.x) {
        const int n  = u & (CH - 1);        // consecutive lanes -> consecutive n (coalesced reads)
        const int k4 = u >> 8;              // 0..47
        float4 q;
        q.x = __uint_as_float(f2tf32(vb[(size_t)(k4 * 4 + 0) * OUTCOLS + n]));
        q.y = __uint_as_float(f2tf32(vb[(size_t)(k4 * 4 + 1) * OUTCOLS + n]));
        q.z = __uint_as_float(f2tf32(vb[(size_t)(k4 * 4 + 2) * OUTCOLS + n]));
        q.w = __uint_as_float(f2tf32(vb[(size_t)(k4 * 4 + 3) * OUTCOLS + n]));
        *reinterpret_cast<float4*>(dst + (size_t)n * KTOT + k4 * 4) = q;
    }
}

// ---------------- main GEMM: tf32 mma.sync ----------------
__global__ void __launch_bounds__(NTHREADS, 2)
tic_mma_kernel(const float* __restrict__ bias, float* __restrict__ out) {
    extern __shared__ char smem[];
    const uint32_t sb = smem_u32(smem);

    const int ct = blockIdx.x;      // 0..1
    const int r  = blockIdx.y;      // 0..48
    const int bt = blockIdx.z;      // 0..63

    const int tid = threadIdx.x;
    const int wid = tid >> 5, lid = tid & 31;
    const int wr = wid >> 2, wc = wid & 3;          // 2 x 4 warps; warp tile 64x32
    const int grp = lid >> 3, lr = lid & 7;

    const int c0 = d_cell[r * 3 + 0] * IN_CH;
    const int c1 = d_cell[r * 3 + 1] * IN_CH;
    const int c2 = d_cell[r * 3 + 2] * IN_CH;

    const float* xb  = d_xR + (size_t)bt * BM * XCOLS;
    const float* vTb = d_vT + (size_t)r * CH * KTOT + (size_t)ct * BN * KTOT;

    // cp.async staging coords: u = tid + it*256; row = u/8, f4 = u%8 (8 x 16B per row)
    const int ld_row = tid >> 3;
    const int ld_f4  = tid & 7;

    // ldmatrix lane base addresses (bytes, relative to tile start)
    //  A frag a0..a3: rows (grp&1)*8+lr, kcol (grp>>1)*4
    const uint32_t aBase = ((wr * 64 + ((grp & 1) << 3) + lr) * ROWSTRIDE + ((grp >> 1) << 2)) * 4;
    //  B frag pairs: n rows (grp>>1)*8+lr, kcol (grp&1)*4
    const uint32_t bBase = ((wc * 32 + ((grp >> 1) << 3) + lr) * ROWSTRIDE + ((grp & 1) << 2)) * 4;

    float acc[4][4][4];
#pragma unroll
    for (int i = 0; i < 4; i++)
#pragma unroll
        for (int j = 0; j < 4; j++)
#pragma unroll
            for (int q = 0; q < 4; q++) acc[i][j][q] = 0.0f;

    // ---- chunk loader ----
    auto load_chunk = [&](int c, int buf) {
        const uint32_t sA = sb + buf * BUF_STRIDE;
        const uint32_t sB = sA + TILE_BYTES;
        const int e = c >> 1;
        const int cellbase = (e == 0 ? c0 : (e == 1 ? c1 : c2)) + (c & 1) * KC;
#pragma unroll
        for (int it = 0; it < 4; it++) {
            const int row = ld_row + it * 32;
            cp_async16(sA + (row * ROWSTRIDE + ld_f4 * 4) * 4,
                       xb + (size_t)row * XCOLS + cellbase + ld_f4 * 4);
        }
#pragma unroll
        for (int it = 0; it < 4; it++) {
            const int n = ld_row + it * 32;
            cp_async16(sB + (n * ROWSTRIDE + ld_f4 * 4) * 4,
                       vTb + (size_t)n * KTOT + c * KC + ld_f4 * 4);
        }
    };

    auto compute = [&](int buf) {
        const uint32_t sA = sb + buf * BUF_STRIDE;
        const uint32_t sB = sA + TILE_BYTES;
#pragma unroll
        for (int ks = 0; ks < 4; ks++) {
            uint32_t af[4][4], bf[4][2];
#pragma unroll
            for (int mt = 0; mt < 4; mt++)
                ldmx4(af[mt], sA + aBase + mt * 16 * ROWSTRIDE * 4 + ks * 32);
#pragma unroll
            for (int np = 0; np < 2; np++) {
                uint32_t t[4];
                ldmx4(t, sB + bBase + np * 16 * ROWSTRIDE * 4 + ks * 32);
                bf[np * 2 + 0][0] = t[0]; bf[np * 2 + 0][1] = t[1];
                bf[np * 2 + 1][0] = t[2]; bf[np * 2 + 1][1] = t[3];
            }
#pragma unroll
            for (int mt = 0; mt < 4; mt++)
#pragma unroll
                for (int nt = 0; nt < 4; nt++)
                    mma_tf32(acc[mt][nt], af[mt], bf[nt]);
        }
    };

    // ---- pipeline ----
    load_chunk(0, 0); CP_COMMIT();
    load_chunk(1, 1); CP_COMMIT();
    CP_WAIT(1);
    __syncthreads();

#pragma unroll 1
    for (int c = 0; c < CHUNKS; c++) {
        compute(c & 1);
        __syncthreads();
        if (c + 2 < CHUNKS) { load_chunk(c + 2, c & 1); CP_COMMIT(); }
        if (c + 1 < CHUNKS) {
            if (c + 2 < CHUNKS) CP_WAIT(1); else CP_WAIT(0);
            __syncthreads();
        }
    }

    // ---- epilogue ----
    const int colbase = r * CH + ct * BN + wc * 32;
    float2 bv[4];
#pragma unroll
    for (int nt = 0; nt < 4; nt++)
        bv[nt] = *reinterpret_cast<const float2*>(bias + colbase + nt * 8 + 2 * (lid & 3));

    const int row_lo = bt * BM + wr * 64 + (lid >> 2);
#pragma unroll
    for (int mt = 0; mt < 4; mt++) {
        float* o0 = out + (size_t)(row_lo + mt * 16) * OUTCOLS + colbase + 2 * (lid & 3);
        float* o1 = o0 + 8 * OUTCOLS;
#pragma unroll
        for (int nt = 0; nt < 4; nt++) {
            float2 v0 = { acc[mt][nt][0] + bv[nt].x, acc[mt][nt][1] + bv[nt].y };
            float2 v1 = { acc[mt][nt][2] + bv[nt].x, acc[mt][nt][3] + bv[nt].y };
            *reinterpret_cast<float2*>(o0 + nt * 8) = v0;
            *reinterpret_cast<float2*>(o1 + nt * 8) = v1;
        }
    }
}

extern "C" void kernel_launch(void* const* d_in, const int* in_sizes, int n_in,
                              void* d_out, int out_size) {
    const float* x = nullptr;
    const float* v = nullptr;
    const float* b = nullptr;
    for (int i = 0; i < n_in; i++) {
        if (in_sizes[i] == BATCH * XCOLS)            x = (const float*)d_in[i];
        else if (in_sizes[i] == 3 * IN_CH * OUTCOLS) v = (const float*)d_in[i];
        else if (in_sizes[i] == OUTCOLS)             b = (const float*)d_in[i];
    }
    float* out = (float*)d_out;

    cudaFuncSetAttribute(tic_mma_kernel,
                         cudaFuncAttributeMaxDynamicSharedMemorySize, SMEM_TOTAL);

    init_cell_kernel<<<1, 32>>>();
    round_x_kernel<<<4096, 256>>>(x);
    build_vT_kernel<<<ROWS, 256>>>(v);

    dim3 grid(CH / BN, ROWS, BATCH / BM);   // (2, 49, 64)
    tic_mma_kernel<<<grid, NTHREADS, SMEM_TOTAL>>>(b, out);
}

// round 4
// speedup vs baseline: 2.8917x; 1.0353x over previous
#include <cuda_runtime.h>
#include <cstdint>

// ---------------- Problem constants ----------------
#define BATCH   8192
#define IN_CH   64
#define XCOLS   1728           // 27*64
#define OUTCOLS 12544          // 49*256
#define ROWS    49
#define CH      256
#define KTOT    192            // 3*64
#define CHUNKS  6
#define KC      32             // K per chunk
#define BM      128
#define BN      128
#define NTHREADS 256
#define STAGES  3

// SMEM: rows padded to 36 floats (144B) -> conflict-free ldmatrix (144 % 128 = 16)
#define ROWSTRIDE 36
#define TILE_BYTES (128 * ROWSTRIDE * 4)       // 18432
#define BUF_STRIDE (2 * TILE_BYTES)            // A+B per stage (36864)
#define SMEM_TOTAL (STAGES * BUF_STRIDE)       // 110592

__device__ int   d_cell[ROWS * 3];
__device__ float d_vT[(size_t)ROWS * CH * KTOT];   // tf32-rounded, [r][n][k] (9.6MB)

// ---------------- helpers ----------------
__device__ __forceinline__ uint32_t smem_u32(const void* p) {
    uint32_t a;
    asm("{ .reg .u64 t; cvta.to.shared.u64 t, %1; cvt.u32.u64 %0, t; }" : "=r"(a) : "l"(p));
    return a;
}
__device__ __forceinline__ uint32_t f2tf32(float f) {
    uint32_t r;
    asm("cvt.rna.tf32.f32 %0, %1;" : "=r"(r) : "f"(f));
    return r;
}
__device__ __forceinline__ void cp_async16(uint32_t dst, const void* src) {
    asm volatile("cp.async.cg.shared.global [%0], [%1], 16;"
                 :: "r"(dst), "l"(__cvta_generic_to_global(src)) : "memory");
}
#define CP_COMMIT() asm volatile("cp.async.commit_group;" ::: "memory")
#define CP_WAIT(n)  asm volatile("cp.async.wait_group %0;" :: "n"(n) : "memory")

__device__ __forceinline__ void ldmx4(uint32_t* r, uint32_t addr) {
    asm volatile("ldmatrix.sync.aligned.m8n8.x4.shared.b16 {%0,%1,%2,%3}, [%4];"
                 : "=r"(r[0]), "=r"(r[1]), "=r"(r[2]), "=r"(r[3]) : "r"(addr));
}
__device__ __forceinline__ void mma_tf32(float* c, const uint32_t* a, const uint32_t* b) {
    asm volatile(
        "mma.sync.aligned.m16n8k8.row.col.f32.tf32.tf32.f32 "
        "{%0,%1,%2,%3}, {%4,%5,%6,%7}, {%8,%9}, {%0,%1,%2,%3};"
        : "+f"(c[0]), "+f"(c[1]), "+f"(c[2]), "+f"(c[3])
        : "r"(a[0]), "r"(a[1]), "r"(a[2]), "r"(a[3]), "r"(b[0]), "r"(b[1]));
}

// ---------------- init: win-line cell table ----------------
__global__ void init_cell_kernel() {
    if (threadIdx.x != 0 || blockIdx.x != 0) return;
    int col = 0, step = 0, x, y, z;
#define PUT(X, Y, Z) do { d_cell[col*3 + step] = (X) + 3*(Y) + 9*(Z); \
                          step = (step + 1) % 3; } while (0)
    for (x = 0; x < 3; x++) {
        for (y = 0; y < 3; y++) { for (z = 0; z < 3; z++) PUT(x,y,z); col++; }
        for (z = 0; z < 3; z++) { for (y = 0; y < 3; y++) PUT(x,y,z); col++; }
        for (y = 0; y < 3; y++) { z = y;     PUT(x,y,z); } col++;
        for (y = 0; y < 3; y++) { z = 2 - y; PUT(x,y,z); } col++;
    }
    for (z = 0; z < 3; z++) {
        for (y = 0; y < 3; y++) { for (x = 0; x < 3; x++) PUT(x,y,z); col++; }
        for (y = 0; y < 3; y++) { x = y;     PUT(x,y,z); } col++;
        for (y = 0; y < 3; y++) { x = 2 - y; PUT(x,y,z); } col++;
    }
    for (y = 0; y < 3; y++) {
        for (z = 0; z < 3; z++) { x = z;     PUT(x,y,z); } col++;
        for (z = 0; z < 3; z++) { x = 2 - z; PUT(x,y,z); } col++;
    }
    for (x = 0; x < 3; x++) { y = x;     z = x;     PUT(x,y,z); } col++;
    for (x = 0; x < 3; x++) { y = 2 - x; z = 2 - x; PUT(x,y,z); } col++;
    for (x = 0; x < 3; x++) { y = x;     z = 2 - x; PUT(x,y,z); } col++;
    for (x = 0; x < 3; x++) { z = x;     y = 2 - x; PUT(x,y,z); } col++;
#undef PUT
}

// ---------------- pre-pass: transpose+round v -> [r][n][k] ----------------
__global__ void build_vT_kernel(const float* __restrict__ v) {
    const int r = blockIdx.x;
    const float* vb = v + (size_t)r * CH;
    float* dst = d_vT + (size_t)r * CH * KTOT;
    for (int u = threadIdx.x; u < CH * (KTOT / 4); u += blockDim.x) {
        const int n  = u & (CH - 1);        // consecutive lanes -> consecutive n (coalesced reads)
        const int k4 = u >> 8;              // 0..47
        float4 q;
        q.x = __uint_as_float(f2tf32(vb[(size_t)(k4 * 4 + 0) * OUTCOLS + n]));
        q.y = __uint_as_float(f2tf32(vb[(size_t)(k4 * 4 + 1) * OUTCOLS + n]));
        q.z = __uint_as_float(f2tf32(vb[(size_t)(k4 * 4 + 2) * OUTCOLS + n]));
        q.w = __uint_as_float(f2tf32(vb[(size_t)(k4 * 4 + 3) * OUTCOLS + n]));
        *reinterpret_cast<float4*>(dst + (size_t)n * KTOT + k4 * 4) = q;
    }
}

// ---------------- main GEMM: tf32 mma.sync, 3-stage cp.async ----------------
__global__ void __launch_bounds__(NTHREADS, 2)
tic_mma_kernel(const float* __restrict__ x,
               const float* __restrict__ bias,
               float* __restrict__ out) {
    extern __shared__ char smem[];
    const uint32_t sb = smem_u32(smem);

    const int ct = blockIdx.x;      // 0..1
    const int r  = blockIdx.y;      // 0..48
    const int bt = blockIdx.z;      // 0..63

    const int tid = threadIdx.x;
    const int wid = tid >> 5, lid = tid & 31;
    const int wr = wid >> 2, wc = wid & 3;          // 2 x 4 warps; warp tile 64x32
    const int grp = lid >> 3, lr = lid & 7;

    const int c0 = d_cell[r * 3 + 0] * IN_CH;
    const int c1 = d_cell[r * 3 + 1] * IN_CH;
    const int c2 = d_cell[r * 3 + 2] * IN_CH;

    const float* xb  = x + (size_t)bt * BM * XCOLS;
    const float* vTb = d_vT + (size_t)r * CH * KTOT + (size_t)ct * BN * KTOT;

    // cp.async staging coords: row = tid/8, f4 = tid%8 (8 x 16B per row)
    const int ld_row = tid >> 3;
    const int ld_f4  = tid & 7;

    // ldmatrix lane base addresses (bytes, relative to tile start)
    const uint32_t aBase = ((wr * 64 + ((grp & 1) << 3) + lr) * ROWSTRIDE + ((grp >> 1) << 2)) * 4;
    const uint32_t bBase = ((wc * 32 + ((grp >> 1) << 3) + lr) * ROWSTRIDE + ((grp & 1) << 2)) * 4;

    float acc[4][4][4];
#pragma unroll
    for (int i = 0; i < 4; i++)
#pragma unroll
        for (int j = 0; j < 4; j++)
#pragma unroll
            for (int q = 0; q < 4; q++) acc[i][j][q] = 0.0f;

    // ---- chunk loader: A gathered raw from x (tf32 cvt happens in regs), B pre-rounded ----
    auto load_chunk = [&](int c, int buf) {
        const uint32_t sA = sb + buf * BUF_STRIDE;
        const uint32_t sB = sA + TILE_BYTES;
        const int e = c >> 1;
        const int cellbase = (e == 0 ? c0 : (e == 1 ? c1 : c2)) + (c & 1) * KC;
#pragma unroll
        for (int it = 0; it < 4; it++) {
            const int row = ld_row + it * 32;
            cp_async16(sA + (row * ROWSTRIDE + ld_f4 * 4) * 4,
                       xb + (size_t)row * XCOLS + cellbase + ld_f4 * 4);
        }
#pragma unroll
        for (int it = 0; it < 4; it++) {
            const int n = ld_row + it * 32;
            cp_async16(sB + (n * ROWSTRIDE + ld_f4 * 4) * 4,
                       vTb + (size_t)n * KTOT + c * KC + ld_f4 * 4);
        }
    };

    auto compute = [&](int buf) {
        const uint32_t sA = sb + buf * BUF_STRIDE;
        const uint32_t sB = sA + TILE_BYTES;
#pragma unroll
        for (int ks = 0; ks < 4; ks++) {
            uint32_t af[4][4], bf[4][2];
#pragma unroll
            for (int mt = 0; mt < 4; mt++) {
                ldmx4(af[mt], sA + aBase + mt * 16 * ROWSTRIDE * 4 + ks * 32);
#pragma unroll
                for (int q = 0; q < 4; q++)
                    af[mt][q] = f2tf32(__uint_as_float(af[mt][q]));   // rna-round A in regs
            }
#pragma unroll
            for (int np = 0; np < 2; np++) {
                uint32_t t[4];
                ldmx4(t, sB + bBase + np * 16 * ROWSTRIDE * 4 + ks * 32);
                bf[np * 2 + 0][0] = t[0]; bf[np * 2 + 0][1] = t[1];
                bf[np * 2 + 1][0] = t[2]; bf[np * 2 + 1][1] = t[3];
            }
#pragma unroll
            for (int mt = 0; mt < 4; mt++)
#pragma unroll
                for (int nt = 0; nt < 4; nt++)
                    mma_tf32(acc[mt][nt], af[mt], bf[nt]);
        }
    };

    // ---- 3-stage pipeline, one barrier per chunk ----
    load_chunk(0, 0); CP_COMMIT();
    load_chunk(1, 1); CP_COMMIT();

#pragma unroll 1
    for (int c = 0; c < CHUNKS - 1; c++) {
        CP_WAIT(1);                 // chunk c resident
        __syncthreads();            // all warps done reading buf (c-1)%3
        if (c + 2 < CHUNKS) { load_chunk(c + 2, (c + 2) % STAGES); CP_COMMIT(); }
        compute(c % STAGES);
    }
    CP_WAIT(0);
    __syncthreads();
    compute((CHUNKS - 1) % STAGES);

    // ---- epilogue ----
    const int colbase = r * CH + ct * BN + wc * 32;
    float2 bv[4];
#pragma unroll
    for (int nt = 0; nt < 4; nt++)
        bv[nt] = *reinterpret_cast<const float2*>(bias + colbase + nt * 8 + 2 * (lid & 3));

    const int row_lo = bt * BM + wr * 64 + (lid >> 2);
#pragma unroll
    for (int mt = 0; mt < 4; mt++) {
        float* o0 = out + (size_t)(row_lo + mt * 16) * OUTCOLS + colbase + 2 * (lid & 3);
        float* o1 = o0 + 8 * OUTCOLS;
#pragma unroll
        for (int nt = 0; nt < 4; nt++) {
            float2 v0 = { acc[mt][nt][0] + bv[nt].x, acc[mt][nt][1] + bv[nt].y };
            float2 v1 = { acc[mt][nt][2] + bv[nt].x, acc[mt][nt][3] + bv[nt].y };
            *reinterpret_cast<float2*>(o0 + nt * 8) = v0;
            *reinterpret_cast<float2*>(o1 + nt * 8) = v1;
        }
    }
}

extern "C" void kernel_launch(void* const* d_in, const int* in_sizes, int n_in,
                              void* d_out, int out_size) {
    const float* x = nullptr;
    const float* v = nullptr;
    const float* b = nullptr;
    for (int i = 0; i < n_in; i++) {
        if (in_sizes[i] == BATCH * XCOLS)            x = (const float*)d_in[i];
        else if (in_sizes[i] == 3 * IN_CH * OUTCOLS) v = (const float*)d_in[i];
        else if (in_sizes[i] == OUTCOLS)             b = (const float*)d_in[i];
    }
    float* out = (float*)d_out;

    cudaFuncSetAttribute(tic_mma_kernel,
                         cudaFuncAttributeMaxDynamicSharedMemorySize, SMEM_TOTAL);

    init_cell_kernel<<<1, 32>>>();
    build_vT_kernel<<<ROWS, 256>>>(v);

    dim3 grid(CH / BN, ROWS, BATCH / BM);   // (2, 49, 64)
    tic_mma_kernel<<<grid, NTHREADS, SMEM_TOTAL>>>(x, b, out);
}

// round 5
// speedup vs baseline: 2.9627x; 1.0246x over previous
#include <cuda_runtime.h>
#include <cstdint>

// ---------------- Problem constants ----------------
#define BATCH   8192
#define IN_CH   64
#define XCOLS   1728           // 27*64
#define OUTCOLS 12544          // 49*256
#define ROWS    49
#define CH      256
#define KTOT    192            // 3*64
#define CHUNKS  6
#define KC      32             // K per chunk
#define BM      128
#define BN      128
#define NTHREADS 512
#define STAGES  3

// SMEM: rows padded to 36 floats (144B) -> conflict-free ldmatrix (144 % 128 = 16)
#define ROWSTRIDE 36
#define TILE_BYTES (128 * ROWSTRIDE * 4)       // 18432
#define BUF_STRIDE (2 * TILE_BYTES)            // A+B per stage (36864)
#define SMEM_TOTAL (STAGES * BUF_STRIDE)       // 110592

__device__ int   d_cell[ROWS * 3];
__device__ float d_vT[(size_t)ROWS * CH * KTOT];   // tf32-rounded, [r][n][k] (9.6MB)

// ---------------- helpers ----------------
__device__ __forceinline__ uint32_t smem_u32(const void* p) {
    uint32_t a;
    asm("{ .reg .u64 t; cvta.to.shared.u64 t, %1; cvt.u32.u64 %0, t; }" : "=r"(a) : "l"(p));
    return a;
}
__device__ __forceinline__ uint32_t f2tf32(float f) {
    uint32_t r;
    asm("cvt.rna.tf32.f32 %0, %1;" : "=r"(r) : "f"(f));
    return r;
}
__device__ __forceinline__ void cp_async16(uint32_t dst, const void* src) {
    asm volatile("cp.async.cg.shared.global [%0], [%1], 16;"
                 :: "r"(dst), "l"(__cvta_generic_to_global(src)) : "memory");
}
#define CP_COMMIT() asm volatile("cp.async.commit_group;" ::: "memory")
#define CP_WAIT(n)  asm volatile("cp.async.wait_group %0;" :: "n"(n) : "memory")

__device__ __forceinline__ void ldmx4(uint32_t* r, uint32_t addr) {
    asm volatile("ldmatrix.sync.aligned.m8n8.x4.shared.b16 {%0,%1,%2,%3}, [%4];"
                 : "=r"(r[0]), "=r"(r[1]), "=r"(r[2]), "=r"(r[3]) : "r"(addr));
}
__device__ __forceinline__ void mma_tf32(float* c, const uint32_t* a, const uint32_t* b) {
    asm volatile(
        "mma.sync.aligned.m16n8k8.row.col.f32.tf32.tf32.f32 "
        "{%0,%1,%2,%3}, {%4,%5,%6,%7}, {%8,%9}, {%0,%1,%2,%3};"
        : "+f"(c[0]), "+f"(c[1]), "+f"(c[2]), "+f"(c[3])
        : "r"(a[0]), "r"(a[1]), "r"(a[2]), "r"(a[3]), "r"(b[0]), "r"(b[1]));
}

// ---------------- pre-pass: cell table + transpose+round v -> [r][n][k] ----------------
__global__ void build_vT_kernel(const float* __restrict__ v) {
    // Fold the win-line cell-table init into block 0 (ordering before GEMM is
    // guaranteed by stream order of the next launch).
    if (blockIdx.x == 0 && threadIdx.x == 0) {
        int col = 0, step = 0, x, y, z;
#define PUT(X, Y, Z) do { d_cell[col*3 + step] = (X) + 3*(Y) + 9*(Z); \
                          step = (step + 1) % 3; } while (0)
        for (x = 0; x < 3; x++) {
            for (y = 0; y < 3; y++) { for (z = 0; z < 3; z++) PUT(x,y,z); col++; }
            for (z = 0; z < 3; z++) { for (y = 0; y < 3; y++) PUT(x,y,z); col++; }
            for (y = 0; y < 3; y++) { z = y;     PUT(x,y,z); } col++;
            for (y = 0; y < 3; y++) { z = 2 - y; PUT(x,y,z); } col++;
        }
        for (z = 0; z < 3; z++) {
            for (y = 0; y < 3; y++) { for (x = 0; x < 3; x++) PUT(x,y,z); col++; }
            for (y = 0; y < 3; y++) { x = y;     PUT(x,y,z); } col++;
            for (y = 0; y < 3; y++) { x = 2 - y; PUT(x,y,z); } col++;
        }
        for (y = 0; y < 3; y++) {
            for (z = 0; z < 3; z++) { x = z;     PUT(x,y,z); } col++;
            for (z = 0; z < 3; z++) { x = 2 - z; PUT(x,y,z); } col++;
        }
        for (x = 0; x < 3; x++) { y = x;     z = x;     PUT(x,y,z); } col++;
        for (x = 0; x < 3; x++) { y = 2 - x; z = 2 - x; PUT(x,y,z); } col++;
        for (x = 0; x < 3; x++) { y = x;     z = 2 - x; PUT(x,y,z); } col++;
        for (x = 0; x < 3; x++) { z = x;     y = 2 - x; PUT(x,y,z); } col++;
#undef PUT
    }
    const int r = blockIdx.x;
    const float* vb = v + (size_t)r * CH;
    float* dst = d_vT + (size_t)r * CH * KTOT;
    for (int u = threadIdx.x; u < CH * (KTOT / 4); u += blockDim.x) {
        const int n  = u & (CH - 1);
        const int k4 = u >> 8;
        float4 q;
        q.x = __uint_as_float(f2tf32(vb[(size_t)(k4 * 4 + 0) * OUTCOLS + n]));
        q.y = __uint_as_float(f2tf32(vb[(size_t)(k4 * 4 + 1) * OUTCOLS + n]));
        q.z = __uint_as_float(f2tf32(vb[(size_t)(k4 * 4 + 2) * OUTCOLS + n]));
        q.w = __uint_as_float(f2tf32(vb[(size_t)(k4 * 4 + 3) * OUTCOLS + n]));
        *reinterpret_cast<float4*>(dst + (size_t)n * KTOT + k4 * 4) = q;
    }
}

// ---------------- main GEMM: tf32 mma.sync, 16 warps, 32x32 warp tile ----------------
__global__ void __launch_bounds__(NTHREADS, 2)
tic_mma_kernel(const float* __restrict__ x,
               const float* __restrict__ bias,
               float* __restrict__ out) {
    extern __shared__ char smem[];
    const uint32_t sb = smem_u32(smem);

    const int ct = blockIdx.x;      // 0..1
    const int r  = blockIdx.y;      // 0..48
    const int bt = blockIdx.z;      // 0..63

    const int tid = threadIdx.x;
    const int wid = tid >> 5, lid = tid & 31;
    const int wr = wid >> 2, wc = wid & 3;          // 4 x 4 warps; warp tile 32x32
    const int grp = lid >> 3, lr = lid & 7;

    const int c0 = d_cell[r * 3 + 0] * IN_CH;
    const int c1 = d_cell[r * 3 + 1] * IN_CH;
    const int c2 = d_cell[r * 3 + 2] * IN_CH;

    const float* xb  = x + (size_t)bt * BM * XCOLS;
    const float* vTb = d_vT + (size_t)r * CH * KTOT + (size_t)ct * BN * KTOT;

    // cp.async staging: 512 threads, 8 x 16B per row -> 64 rows/iter, 2 iters
    const int ld_row = tid >> 3;          // 0..63
    const int ld_f4  = tid & 7;

    // ldmatrix lane base addresses (bytes, relative to tile start)
    const uint32_t aBase = ((wr * 32 + ((grp & 1) << 3) + lr) * ROWSTRIDE + ((grp >> 1) << 2)) * 4;
    const uint32_t bBase = ((wc * 32 + ((grp >> 1) << 3) + lr) * ROWSTRIDE + ((grp & 1) << 2)) * 4;

    float acc[2][4][4];
#pragma unroll
    for (int i = 0; i < 2; i++)
#pragma unroll
        for (int j = 0; j < 4; j++)
#pragma unroll
            for (int q = 0; q < 4; q++) acc[i][j][q] = 0.0f;

    // ---- chunk loader: A gathered raw from x (tf32 cvt in regs), B pre-rounded ----
    auto load_chunk = [&](int c, int buf) {
        const uint32_t sA = sb + buf * BUF_STRIDE;
        const uint32_t sB = sA + TILE_BYTES;
        const int e = c >> 1;
        const int cellbase = (e == 0 ? c0 : (e == 1 ? c1 : c2)) + (c & 1) * KC;
#pragma unroll
        for (int it = 0; it < 2; it++) {
            const int row = ld_row + it * 64;
            cp_async16(sA + (row * ROWSTRIDE + ld_f4 * 4) * 4,
                       xb + (size_t)row * XCOLS + cellbase + ld_f4 * 4);
        }
#pragma unroll
        for (int it = 0; it < 2; it++) {
            const int n = ld_row + it * 64;
            cp_async16(sB + (n * ROWSTRIDE + ld_f4 * 4) * 4,
                       vTb + (size_t)n * KTOT + c * KC + ld_f4 * 4);
        }
    };

    auto compute = [&](int buf) {
        const uint32_t sA = sb + buf * BUF_STRIDE;
        const uint32_t sB = sA + TILE_BYTES;
#pragma unroll
        for (int ks = 0; ks < 4; ks++) {
            uint32_t af[2][4], bf[4][2];
#pragma unroll
            for (int mt = 0; mt < 2; mt++) {
                ldmx4(af[mt], sA + aBase + mt * 16 * ROWSTRIDE * 4 + ks * 32);
#pragma unroll
                for (int q = 0; q < 4; q++)
                    af[mt][q] = f2tf32(__uint_as_float(af[mt][q]));
            }
#pragma unroll
            for (int np = 0; np < 2; np++) {
                uint32_t t[4];
                ldmx4(t, sB + bBase + np * 16 * ROWSTRIDE * 4 + ks * 32);
                bf[np * 2 + 0][0] = t[0]; bf[np * 2 + 0][1] = t[1];
                bf[np * 2 + 1][0] = t[2]; bf[np * 2 + 1][1] = t[3];
            }
#pragma unroll
            for (int mt = 0; mt < 2; mt++)
#pragma unroll
                for (int nt = 0; nt < 4; nt++)
                    mma_tf32(acc[mt][nt], af[mt], bf[nt]);
        }
    };

    // ---- 3-stage pipeline, one barrier per chunk ----
    load_chunk(0, 0); CP_COMMIT();
    load_chunk(1, 1); CP_COMMIT();

#pragma unroll 1
    for (int c = 0; c < CHUNKS - 1; c++) {
        CP_WAIT(1);
        __syncthreads();
        if (c + 2 < CHUNKS) { load_chunk(c + 2, (c + 2) % STAGES); CP_COMMIT(); }
        compute(c % STAGES);
    }
    CP_WAIT(0);
    __syncthreads();
    compute((CHUNKS - 1) % STAGES);

    // ---- epilogue ----
    const int colbase = r * CH + ct * BN + wc * 32;
    float2 bv[4];
#pragma unroll
    for (int nt = 0; nt < 4; nt++)
        bv[nt] = *reinterpret_cast<const float2*>(bias + colbase + nt * 8 + 2 * (lid & 3));

    const int row_lo = bt * BM + wr * 32 + (lid >> 2);
#pragma unroll
    for (int mt = 0; mt < 2; mt++) {
        float* o0 = out + (size_t)(row_lo + mt * 16) * OUTCOLS + colbase + 2 * (lid & 3);
        float* o1 = o0 + 8 * OUTCOLS;
#pragma unroll
        for (int nt = 0; nt < 4; nt++) {
            float2 v0 = { acc[mt][nt][0] + bv[nt].x, acc[mt][nt][1] + bv[nt].y };
            float2 v1 = { acc[mt][nt][2] + bv[nt].x, acc[mt][nt][3] + bv[nt].y };
            *reinterpret_cast<float2*>(o0 + nt * 8) = v0;
            *reinterpret_cast<float2*>(o1 + nt * 8) = v1;
        }
    }
}

extern "C" void kernel_launch(void* const* d_in, const int* in_sizes, int n_in,
                              void* d_out, int out_size) {
    const float* x = nullptr;
    const float* v = nullptr;
    const float* b = nullptr;
    for (int i = 0; i < n_in; i++) {
        if (in_sizes[i] == BATCH * XCOLS)            x = (const float*)d_in[i];
        else if (in_sizes[i] == 3 * IN_CH * OUTCOLS) v = (const float*)d_in[i];
        else if (in_sizes[i] == OUTCOLS)             b = (const float*)d_in[i];
    }
    float* out = (float*)d_out;

    cudaFuncSetAttribute(tic_mma_kernel,
                         cudaFuncAttributeMaxDynamicSharedMemorySize, SMEM_TOTAL);

    build_vT_kernel<<<ROWS, 256>>>(v);

    dim3 grid(CH / BN, ROWS, BATCH / BM);   // (2, 49, 64)
    tic_mma_kernel<<<grid, NTHREADS, SMEM_TOTAL>>>(x, b, out);
}

// round 7
// speedup vs baseline: 4.4639x; 1.5067x over previous
#include <cuda_runtime.h>
#include <cuda_fp16.h>
#include <cstdint>
#include <cstring>

// ---------------- Problem constants ----------------
#define BATCH   8192
#define IN_CH   64
#define XCOLS   1728           // 27*64
#define OUTCOLS 12544          // 49*256
#define ROWS    49
#define CH      256
#define KTOT    192            // 3*64
#define CHUNKS  3
#define KC      64             // K (halves) per chunk == one board cell
#define BM      128
#define BN      128
#define NTHREADS 512

// SMEM: fp16 rows of 64 data halves padded to 72 (144B) -> conflict-free ldmatrix
#define RSH     72
#define TILE_BYTES (128 * RSH * 2)             // 18432
#define BUF_STRIDE (2 * TILE_BYTES)            // A+B per stage (36864)
#define SMEM_TOTAL (CHUNKS * BUF_STRIDE)       // 110592

__device__ int    d_cell[ROWS * 3];
__device__ __align__(16) __half d_xH[(size_t)BATCH * XCOLS];        // 28.3MB
__device__ __align__(16) __half d_vTH[(size_t)ROWS * CH * KTOT];    // 4.8MB, [r][n][k]

// ---------------- helpers ----------------
__device__ __forceinline__ uint32_t h2_as_u32(__half2 h) {
    uint32_t u;
    memcpy(&u, &h, 4);
    return u;
}
__device__ __forceinline__ uint32_t smem_u32(const void* p) {
    uint32_t a;
    asm("{ .reg .u64 t; cvta.to.shared.u64 t, %1; cvt.u32.u64 %0, t; }" : "=r"(a) : "l"(p));
    return a;
}
__device__ __forceinline__ void cp_async16(uint32_t dst, const void* src) {
    asm volatile("cp.async.cg.shared.global [%0], [%1], 16;"
                 :: "r"(dst), "l"(__cvta_generic_to_global(src)) : "memory");
}
#define CP_COMMIT() asm volatile("cp.async.commit_group;" ::: "memory")
#define CP_WAIT(n)  asm volatile("cp.async.wait_group %0;" :: "n"(n) : "memory")

__device__ __forceinline__ void ldmx4(uint32_t* r, uint32_t addr) {
    asm volatile("ldmatrix.sync.aligned.m8n8.x4.shared.b16 {%0,%1,%2,%3}, [%4];"
                 : "=r"(r[0]), "=r"(r[1]), "=r"(r[2]), "=r"(r[3]) : "r"(addr));
}
__device__ __forceinline__ void mma_f16(float* c, const uint32_t* a, const uint32_t* b) {
    asm volatile(
        "mma.sync.aligned.m16n8k16.row.col.f32.f16.f16.f32 "
        "{%0,%1,%2,%3}, {%4,%5,%6,%7}, {%8,%9}, {%0,%1,%2,%3};"
        : "+f"(c[0]), "+f"(c[1]), "+f"(c[2]), "+f"(c[3])
        : "r"(a[0]), "r"(a[1]), "r"(a[2]), "r"(a[3]), "r"(b[0]), "r"(b[1]));
}

// ---------------- pre-pass 1: x -> fp16, plus cell table ----------------
__global__ void conv_x_kernel(const float* __restrict__ x) {
    if (blockIdx.x == 0 && threadIdx.x == 0) {
        int col = 0, step = 0, xx, yy, zz;
#define PUT(X, Y, Z) do { d_cell[col*3 + step] = (X) + 3*(Y) + 9*(Z); \
                          step = (step + 1) % 3; } while (0)
        for (xx = 0; xx < 3; xx++) {
            for (yy = 0; yy < 3; yy++) { for (zz = 0; zz < 3; zz++) PUT(xx,yy,zz); col++; }
            for (zz = 0; zz < 3; zz++) { for (yy = 0; yy < 3; yy++) PUT(xx,yy,zz); col++; }
            for (yy = 0; yy < 3; yy++) { zz = yy;     PUT(xx,yy,zz); } col++;
            for (yy = 0; yy < 3; yy++) { zz = 2 - yy; PUT(xx,yy,zz); } col++;
        }
        for (zz = 0; zz < 3; zz++) {
            for (yy = 0; yy < 3; yy++) { for (xx = 0; xx < 3; xx++) PUT(xx,yy,zz); col++; }
            for (yy = 0; yy < 3; yy++) { xx = yy;     PUT(xx,yy,zz); } col++;
            for (yy = 0; yy < 3; yy++) { xx = 2 - yy; PUT(xx,yy,zz); } col++;
        }
        for (yy = 0; yy < 3; yy++) {
            for (zz = 0; zz < 3; zz++) { xx = zz;     PUT(xx,yy,zz); } col++;
            for (zz = 0; zz < 3; zz++) { xx = 2 - zz; PUT(xx,yy,zz); } col++;
        }
        for (xx = 0; xx < 3; xx++) { yy = xx;     zz = xx;     PUT(xx,yy,zz); } col++;
        for (xx = 0; xx < 3; xx++) { yy = 2 - xx; zz = 2 - xx; PUT(xx,yy,zz); } col++;
        for (xx = 0; xx < 3; xx++) { yy = xx;     zz = 2 - xx; PUT(xx,yy,zz); } col++;
        for (xx = 0; xx < 3; xx++) { zz = xx;     yy = 2 - xx; PUT(xx,yy,zz); } col++;
#undef PUT
    }
    const size_t n8 = (size_t)BATCH * XCOLS / 8;
    const float4* src = reinterpret_cast<const float4*>(x);
    uint4* dst = reinterpret_cast<uint4*>(d_xH);
    for (size_t i = blockIdx.x * (size_t)blockDim.x + threadIdx.x;
         i < n8; i += (size_t)gridDim.x * blockDim.x) {
        float4 a = src[2 * i], b = src[2 * i + 1];
        uint4 o;
        o.x = h2_as_u32(__floats2half2_rn(a.x, a.y));
        o.y = h2_as_u32(__floats2half2_rn(a.z, a.w));
        o.z = h2_as_u32(__floats2half2_rn(b.x, b.y));
        o.w = h2_as_u32(__floats2half2_rn(b.z, b.w));
        dst[i] = o;
    }
}

// ---------------- pre-pass 2: v -> transposed fp16 [r][n][k] ----------------
__global__ void build_vT_kernel(const float* __restrict__ v) {
    const int r = blockIdx.x;
    const float* vb = v + (size_t)r * CH;
    __half* dst = d_vTH + (size_t)r * CH * KTOT;
    for (int u = threadIdx.x; u < CH * (KTOT / 8); u += blockDim.x) {
        const int n  = u & (CH - 1);         // lanes -> consecutive n (coalesced reads)
        const int k8 = u >> 8;               // 0..23
        uint4 o;
        uint32_t h[4];
#pragma unroll
        for (int p = 0; p < 4; p++) {
            float lo = vb[(size_t)(k8 * 8 + 2 * p + 0) * OUTCOLS + n];
            float hi = vb[(size_t)(k8 * 8 + 2 * p + 1) * OUTCOLS + n];
            h[p] = h2_as_u32(__floats2half2_rn(lo, hi));
        }
        o.x = h[0]; o.y = h[1]; o.z = h[2]; o.w = h[3];
        *reinterpret_cast<uint4*>(dst + (size_t)n * KTOT + k8 * 8) = o;
    }
}

// ---------------- main GEMM: fp16 mma.sync m16n8k16 ----------------
__global__ void __launch_bounds__(NTHREADS, 2)
tic_mma_kernel(const float* __restrict__ bias, float* __restrict__ out) {
    extern __shared__ char smem[];
    const uint32_t sb = smem_u32(smem);

    const int ct = blockIdx.x;      // 0..1
    const int r  = blockIdx.y;      // 0..48
    const int bt = blockIdx.z;      // 0..63

    const int tid = threadIdx.x;
    const int wid = tid >> 5, lid = tid & 31;
    const int wr = wid >> 2, wc = wid & 3;          // 4 x 4 warps; warp tile 32x32
    const int grp = lid >> 3, lr = lid & 7;

    const __half* xb  = d_xH + (size_t)bt * BM * XCOLS;
    const __half* vTb = d_vTH + (size_t)r * CH * KTOT + (size_t)ct * BN * KTOT;

    // staging: 64 rows/iter (512 thr / 8 per row), 8 x 16B per 128B row
    const int ld_row = tid >> 3;          // 0..63
    const int ld_f4  = tid & 7;

    // ldmatrix bases (bytes): quadrants (r,k0),(r+8,k0),(r,k8),(r+8,k8)
    const uint32_t aBase = ((wr * 32 + ((grp & 1) << 3) + lr) * RSH + ((grp >> 1) << 3)) * 2;
    const uint32_t bBase = ((wc * 32 + ((grp & 1) << 3) + lr) * RSH + ((grp >> 1) << 3)) * 2;

    float acc[2][4][4];
#pragma unroll
    for (int i = 0; i < 2; i++)
#pragma unroll
        for (int j = 0; j < 4; j++)
#pragma unroll
            for (int q = 0; q < 4; q++) acc[i][j][q] = 0.0f;

    // ---- load all 3 chunks up-front (no buffer reuse) ----
#pragma unroll
    for (int c = 0; c < CHUNKS; c++) {
        const uint32_t sA = sb + c * BUF_STRIDE;
        const uint32_t sB = sA + TILE_BYTES;
        const int cellbase = d_cell[r * 3 + c] * IN_CH;   // halves offset into x row
#pragma unroll
        for (int it = 0; it < 2; it++) {
            const int row = ld_row + it * 64;
            cp_async16(sA + row * (RSH * 2) + ld_f4 * 16,
                       xb + (size_t)row * XCOLS + cellbase + ld_f4 * 8);
        }
#pragma unroll
        for (int it = 0; it < 2; it++) {
            const int n = ld_row + it * 64;
            cp_async16(sB + n * (RSH * 2) + ld_f4 * 16,
                       vTb + (size_t)n * KTOT + c * KC + ld_f4 * 8);
        }
        CP_COMMIT();
    }

    // ---- compute chunks as they land ----
#pragma unroll
    for (int c = 0; c < CHUNKS; c++) {
        if (c == 0)      CP_WAIT(2);
        else if (c == 1) CP_WAIT(1);
        else             CP_WAIT(0);
        __syncthreads();

        const uint32_t sA = sb + c * BUF_STRIDE;
        const uint32_t sB = sA + TILE_BYTES;
#pragma unroll
        for (int ks = 0; ks < 4; ks++) {            // 4 x k16 per chunk
            uint32_t af[2][4], bf[4][2];
#pragma unroll
            for (int mt = 0; mt < 2; mt++)
                ldmx4(af[mt], sA + aBase + mt * 16 * RSH * 2 + ks * 32);
#pragma unroll
            for (int np = 0; np < 2; np++) {
                uint32_t t[4];
                ldmx4(t, sB + bBase + np * 16 * RSH * 2 + ks * 32);
                bf[np * 2 + 0][0] = t[0]; bf[np * 2 + 0][1] = t[2];   // n group lo: {b0,b1}
                bf[np * 2 + 1][0] = t[1]; bf[np * 2 + 1][1] = t[3];   // n group hi
            }
#pragma unroll
            for (int mt = 0; mt < 2; mt++)
#pragma unroll
                for (int nt = 0; nt < 4; nt++)
                    mma_f16(acc[mt][nt], af[mt], bf[nt]);
        }
    }

    // ---- epilogue ----
    const int colbase = r * CH + ct * BN + wc * 32;
    float2 bv[4];
#pragma unroll
    for (int nt = 0; nt < 4; nt++)
        bv[nt] = *reinterpret_cast<const float2*>(bias + colbase + nt * 8 + 2 * (lid & 3));

    const int row_lo = bt * BM + wr * 32 + (lid >> 2);
#pragma unroll
    for (int mt = 0; mt < 2; mt++) {
        float* o0 = out + (size_t)(row_lo + mt * 16) * OUTCOLS + colbase + 2 * (lid & 3);
        float* o1 = o0 + 8 * OUTCOLS;
#pragma unroll
        for (int nt = 0; nt < 4; nt++) {
            float2 v0 = { acc[mt][nt][0] + bv[nt].x, acc[mt][nt][1] + bv[nt].y };
            float2 v1 = { acc[mt][nt][2] + bv[nt].x, acc[mt][nt][3] + bv[nt].y };
            *reinterpret_cast<float2*>(o0 + nt * 8) = v0;
            *reinterpret_cast<float2*>(o1 + nt * 8) = v1;
        }
    }
}

extern "C" void kernel_launch(void* const* d_in, const int* in_sizes, int n_in,
                              void* d_out, int out_size) {
    const float* x = nullptr;
    const float* v = nullptr;
    const float* b = nullptr;
    for (int i = 0; i < n_in; i++) {
        if (in_sizes[i] == BATCH * XCOLS)            x = (const float*)d_in[i];
        else if (in_sizes[i] == 3 * IN_CH * OUTCOLS) v = (const float*)d_in[i];
        else if (in_sizes[i] == OUTCOLS)             b = (const float*)d_in[i];
    }
    float* out = (float*)d_out;

    cudaFuncSetAttribute(tic_mma_kernel,
                         cudaFuncAttributeMaxDynamicSharedMemorySize, SMEM_TOTAL);

    conv_x_kernel<<<2048, 256>>>(x);
    build_vT_kernel<<<ROWS, 256>>>(v);

    dim3 grid(CH / BN, ROWS, BATCH / BM);   // (2, 49, 64)
    tic_mma_kernel<<<grid, NTHREADS, SMEM_TOTAL>>>(b, out);
}

// round 8
// speedup vs baseline: 4.5290x; 1.0146x over previous
#include <cuda_runtime.h>
#include <cuda_fp16.h>
#include <cstdint>
#include <cstring>

// ---------------- Problem constants ----------------
#define BATCH   8192
#define IN_CH   64
#define XCOLS   1728           // 27*64
#define OUTCOLS 12544          // 49*256
#define ROWS    49
#define CH      256
#define KTOT    192            // 3*64
#define CHUNKS  3
#define KC      64             // K (halves) per chunk == one board cell
#define BM      128
#define BN      128
#define NTHREADS 512

// SMEM: fp16 rows of 64 data halves padded to 72 (144B) -> conflict-free ldmatrix
#define RSH     72
#define TILE_BYTES (128 * RSH * 2)             // 18432
#define BUF_STRIDE (2 * TILE_BYTES)            // A+B per stage (36864)
#define SMEM_TOTAL (CHUNKS * BUF_STRIDE)       // 110592

__device__ int    d_cell[ROWS * 3];
__device__ __align__(16) __half d_xH[(size_t)BATCH * XCOLS];        // 28.3MB
__device__ __align__(16) __half d_vTH[(size_t)ROWS * CH * KTOT];    // 4.8MB, [r][n][k]

// ---------------- helpers ----------------
__device__ __forceinline__ uint32_t h2_as_u32(__half2 h) {
    uint32_t u;
    memcpy(&u, &h, 4);
    return u;
}
__device__ __forceinline__ uint32_t smem_u32(const void* p) {
    uint32_t a;
    asm("{ .reg .u64 t; cvta.to.shared.u64 t, %1; cvt.u32.u64 %0, t; }" : "=r"(a) : "l"(p));
    return a;
}
__device__ __forceinline__ void cp_async16(uint32_t dst, const void* src) {
    asm volatile("cp.async.cg.shared.global [%0], [%1], 16;"
                 :: "r"(dst), "l"(__cvta_generic_to_global(src)) : "memory");
}
#define CP_COMMIT() asm volatile("cp.async.commit_group;" ::: "memory")
#define CP_WAIT(n)  asm volatile("cp.async.wait_group %0;" :: "n"(n) : "memory")

__device__ __forceinline__ void ldmx4(uint32_t* r, uint32_t addr) {
    asm volatile("ldmatrix.sync.aligned.m8n8.x4.shared.b16 {%0,%1,%2,%3}, [%4];"
                 : "=r"(r[0]), "=r"(r[1]), "=r"(r[2]), "=r"(r[3]) : "r"(addr));
}
__device__ __forceinline__ void mma_f16(float* c, const uint32_t* a, const uint32_t* b) {
    asm volatile(
        "mma.sync.aligned.m16n8k16.row.col.f32.f16.f16.f32 "
        "{%0,%1,%2,%3}, {%4,%5,%6,%7}, {%8,%9}, {%0,%1,%2,%3};"
        : "+f"(c[0]), "+f"(c[1]), "+f"(c[2]), "+f"(c[3])
        : "r"(a[0]), "r"(a[1]), "r"(a[2]), "r"(a[3]), "r"(b[0]), "r"(b[1]));
}

// ---------------- single merged pre-pass ----------------
// block 0 / thread 0: cell table
// blocks [0, ROWS): v transpose+round for line r = blockIdx.x
// all blocks: strided x -> fp16 conversion
__global__ void prepass_kernel(const float* __restrict__ x,
                               const float* __restrict__ v) {
    if (blockIdx.x == 0 && threadIdx.x == 0) {
        int col = 0, step = 0, xx, yy, zz;
#define PUT(X, Y, Z) do { d_cell[col*3 + step] = (X) + 3*(Y) + 9*(Z); \
                          step = (step + 1) % 3; } while (0)
        for (xx = 0; xx < 3; xx++) {
            for (yy = 0; yy < 3; yy++) { for (zz = 0; zz < 3; zz++) PUT(xx,yy,zz); col++; }
            for (zz = 0; zz < 3; zz++) { for (yy = 0; yy < 3; yy++) PUT(xx,yy,zz); col++; }
            for (yy = 0; yy < 3; yy++) { zz = yy;     PUT(xx,yy,zz); } col++;
            for (yy = 0; yy < 3; yy++) { zz = 2 - yy; PUT(xx,yy,zz); } col++;
        }
        for (zz = 0; zz < 3; zz++) {
            for (yy = 0; yy < 3; yy++) { for (xx = 0; xx < 3; xx++) PUT(xx,yy,zz); col++; }
            for (yy = 0; yy < 3; yy++) { xx = yy;     PUT(xx,yy,zz); } col++;
            for (yy = 0; yy < 3; yy++) { xx = 2 - yy; PUT(xx,yy,zz); } col++;
        }
        for (yy = 0; yy < 3; yy++) {
            for (zz = 0; zz < 3; zz++) { xx = zz;     PUT(xx,yy,zz); } col++;
            for (zz = 0; zz < 3; zz++) { xx = 2 - zz; PUT(xx,yy,zz); } col++;
        }
        for (xx = 0; xx < 3; xx++) { yy = xx;     zz = xx;     PUT(xx,yy,zz); } col++;
        for (xx = 0; xx < 3; xx++) { yy = 2 - xx; zz = 2 - xx; PUT(xx,yy,zz); } col++;
        for (xx = 0; xx < 3; xx++) { yy = xx;     zz = 2 - xx; PUT(xx,yy,zz); } col++;
        for (xx = 0; xx < 3; xx++) { zz = xx;     yy = 2 - xx; PUT(xx,yy,zz); } col++;
#undef PUT
    }

    // --- v transpose+round: blocks [0, ROWS) ---
    if (blockIdx.x < ROWS) {
        const int r = blockIdx.x;
        const float* vb = v + (size_t)r * CH;
        __half* dst = d_vTH + (size_t)r * CH * KTOT;
        for (int u = threadIdx.x; u < CH * (KTOT / 8); u += blockDim.x) {
            const int n  = u & (CH - 1);
            const int k8 = u >> 8;
            uint4 o;
            uint32_t h[4];
#pragma unroll
            for (int p = 0; p < 4; p++) {
                float lo = vb[(size_t)(k8 * 8 + 2 * p + 0) * OUTCOLS + n];
                float hi = vb[(size_t)(k8 * 8 + 2 * p + 1) * OUTCOLS + n];
                h[p] = h2_as_u32(__floats2half2_rn(lo, hi));
            }
            o.x = h[0]; o.y = h[1]; o.z = h[2]; o.w = h[3];
            *reinterpret_cast<uint4*>(dst + (size_t)n * KTOT + k8 * 8) = o;
        }
    }

    // --- x -> fp16: all blocks, grid-strided ---
    const size_t n8 = (size_t)BATCH * XCOLS / 8;
    const float4* src = reinterpret_cast<const float4*>(x);
    uint4* dst = reinterpret_cast<uint4*>(d_xH);
    for (size_t i = blockIdx.x * (size_t)blockDim.x + threadIdx.x;
         i < n8; i += (size_t)gridDim.x * blockDim.x) {
        float4 a = src[2 * i], b = src[2 * i + 1];
        uint4 o;
        o.x = h2_as_u32(__floats2half2_rn(a.x, a.y));
        o.y = h2_as_u32(__floats2half2_rn(a.z, a.w));
        o.z = h2_as_u32(__floats2half2_rn(b.x, b.y));
        o.w = h2_as_u32(__floats2half2_rn(b.z, b.w));
        dst[i] = o;
    }
}

// ---------------- main GEMM: fp16 mma.sync m16n8k16 ----------------
__global__ void __launch_bounds__(NTHREADS, 2)
tic_mma_kernel(const float* __restrict__ bias, float* __restrict__ out) {
    extern __shared__ char smem[];
    const uint32_t sb = smem_u32(smem);

    const int ct = blockIdx.x;      // 0..1
    const int r  = blockIdx.y;      // 0..48
    const int bt = blockIdx.z;      // 0..63

    const int tid = threadIdx.x;
    const int wid = tid >> 5, lid = tid & 31;
    const int wr = wid >> 2, wc = wid & 3;          // 4 x 4 warps; warp tile 32x32
    const int grp = lid >> 3, lr = lid & 7;

    const __half* xb  = d_xH + (size_t)bt * BM * XCOLS;
    const __half* vTb = d_vTH + (size_t)r * CH * KTOT + (size_t)ct * BN * KTOT;

    // staging: 64 rows/iter (512 thr / 8 per row), 8 x 16B per 128B row
    const int ld_row = tid >> 3;          // 0..63
    const int ld_f4  = tid & 7;

    // ldmatrix bases (bytes): quadrants (r,k0),(r+8,k0),(r,k8),(r+8,k8)
    const uint32_t aBase = ((wr * 32 + ((grp & 1) << 3) + lr) * RSH + ((grp >> 1) << 3)) * 2;
    const uint32_t bBase = ((wc * 32 + ((grp & 1) << 3) + lr) * RSH + ((grp >> 1) << 3)) * 2;

    // ---- load all 3 chunks up-front (no buffer reuse) ----
#pragma unroll
    for (int c = 0; c < CHUNKS; c++) {
        const uint32_t sA = sb + c * BUF_STRIDE;
        const uint32_t sB = sA + TILE_BYTES;
        const int cellbase = d_cell[r * 3 + c] * IN_CH;   // halves offset into x row
#pragma unroll
        for (int it = 0; it < 2; it++) {
            const int row = ld_row + it * 64;
            cp_async16(sA + row * (RSH * 2) + ld_f4 * 16,
                       xb + (size_t)row * XCOLS + cellbase + ld_f4 * 8);
        }
#pragma unroll
        for (int it = 0; it < 2; it++) {
            const int n = ld_row + it * 64;
            cp_async16(sB + n * (RSH * 2) + ld_f4 * 16,
                       vTb + (size_t)n * KTOT + c * KC + ld_f4 * 8);
        }
        CP_COMMIT();
    }

    // ---- bias loads hoisted: hide their latency under the MMA stream ----
    const int colbase = r * CH + ct * BN + wc * 32;
    float2 bv[4];
#pragma unroll
    for (int nt = 0; nt < 4; nt++)
        bv[nt] = *reinterpret_cast<const float2*>(bias + colbase + nt * 8 + 2 * (lid & 3));

    float acc[2][4][4];
#pragma unroll
    for (int i = 0; i < 2; i++)
#pragma unroll
        for (int j = 0; j < 4; j++)
#pragma unroll
            for (int q = 0; q < 4; q++) acc[i][j][q] = 0.0f;

    // ---- compute chunks as they land ----
#pragma unroll
    for (int c = 0; c < CHUNKS; c++) {
        if (c == 0)      CP_WAIT(2);
        else if (c == 1) CP_WAIT(1);
        else             CP_WAIT(0);
        __syncthreads();

        const uint32_t sA = sb + c * BUF_STRIDE;
        const uint32_t sB = sA + TILE_BYTES;
#pragma unroll
        for (int ks = 0; ks < 4; ks++) {            // 4 x k16 per chunk
            uint32_t af[2][4], bf[4][2];
#pragma unroll
            for (int mt = 0; mt < 2; mt++)
                ldmx4(af[mt], sA + aBase + mt * 16 * RSH * 2 + ks * 32);
#pragma unroll
            for (int np = 0; np < 2; np++) {
                uint32_t t[4];
                ldmx4(t, sB + bBase + np * 16 * RSH * 2 + ks * 32);
                bf[np * 2 + 0][0] = t[0]; bf[np * 2 + 0][1] = t[2];   // n group lo: {b0,b1}
                bf[np * 2 + 1][0] = t[1]; bf[np * 2 + 1][1] = t[3];   // n group hi
            }
#pragma unroll
            for (int mt = 0; mt < 2; mt++)
#pragma unroll
                for (int nt = 0; nt < 4; nt++)
                    mma_f16(acc[mt][nt], af[mt], bf[nt]);
        }
    }

    // ---- epilogue ----
    const int row_lo = bt * BM + wr * 32 + (lid >> 2);
#pragma unroll
    for (int mt = 0; mt < 2; mt++) {
        float* o0 = out + (size_t)(row_lo + mt * 16) * OUTCOLS + colbase + 2 * (lid & 3);
        float* o1 = o0 + 8 * OUTCOLS;
#pragma unroll
        for (int nt = 0; nt < 4; nt++) {
            float2 v0 = { acc[mt][nt][0] + bv[nt].x, acc[mt][nt][1] + bv[nt].y };
            float2 v1 = { acc[mt][nt][2] + bv[nt].x, acc[mt][nt][3] + bv[nt].y };
            *reinterpret_cast<float2*>(o0 + nt * 8) = v0;
            *reinterpret_cast<float2*>(o1 + nt * 8) = v1;
        }
    }
}

extern "C" void kernel_launch(void* const* d_in, const int* in_sizes, int n_in,
                              void* d_out, int out_size) {
    const float* x = nullptr;
    const float* v = nullptr;
    const float* b = nullptr;
    for (int i = 0; i < n_in; i++) {
        if (in_sizes[i] == BATCH * XCOLS)            x = (const float*)d_in[i];
        else if (in_sizes[i] == 3 * IN_CH * OUTCOLS) v = (const float*)d_in[i];
        else if (in_sizes[i] == OUTCOLS)             b = (const float*)d_in[i];
    }
    float* out = (float*)d_out;

    cudaFuncSetAttribute(tic_mma_kernel,
                         cudaFuncAttributeMaxDynamicSharedMemorySize, SMEM_TOTAL);

    prepass_kernel<<<2048, 256>>>(x, v);

    dim3 grid(CH / BN, ROWS, BATCH / BM);   // (2, 49, 64)
    tic_mma_kernel<<<grid, NTHREADS, SMEM_TOTAL>>>(b, out);
}

// round 9
// speedup vs baseline: 4.5489x; 1.0044x over previous
#include <cuda_runtime.h>
#include <cuda_fp16.h>
#include <cstdint>
#include <cstring>

// ---------------- Problem constants ----------------
#define BATCH   8192
#define IN_CH   64
#define XCOLS   1728           // 27*64
#define OUTCOLS 12544          // 49*256
#define ROWS    49
#define CH      256
#define KTOT    192            // 3*64
#define CHUNKS  3
#define KC      64             // K (halves) per chunk == one board cell
#define BM      128
#define BN      256
#define NTHREADS 512
#define NGRP    6              // batch-tile groups (CTAs per row-line)

// SMEM: fp16 rows of 64 data halves padded to 72 (144B) -> conflict-free ldmatrix
#define RSH       72
#define ROWB      (RSH * 2)                    // 144 bytes per row
#define A_CHUNK   (BM * ROWB)                  // 18432
#define B_CHUNK   (BN * ROWB)                  // 36864
#define A_BUF     (CHUNKS * A_CHUNK)           // 55296
#define OFF_B     (2 * A_BUF)                  // 110592
#define SMEM_TOTAL (OFF_B + CHUNKS * B_CHUNK)  // 221184

__device__ int    d_cell[ROWS * 3];
__device__ __align__(16) __half d_xH[(size_t)BATCH * XCOLS];        // 28.3MB
__device__ __align__(16) __half d_vTH[(size_t)ROWS * CH * KTOT];    // 4.8MB, [r][n][k]

// ---------------- helpers ----------------
__device__ __forceinline__ uint32_t h2_as_u32(__half2 h) {
    uint32_t u;
    memcpy(&u, &h, 4);
    return u;
}
__device__ __forceinline__ uint32_t smem_u32(const void* p) {
    uint32_t a;
    asm("{ .reg .u64 t; cvta.to.shared.u64 t, %1; cvt.u32.u64 %0, t; }" : "=r"(a) : "l"(p));
    return a;
}
__device__ __forceinline__ void cp_async16(uint32_t dst, const void* src) {
    asm volatile("cp.async.cg.shared.global [%0], [%1], 16;"
                 :: "r"(dst), "l"(__cvta_generic_to_global(src)) : "memory");
}
#define CP_COMMIT() asm volatile("cp.async.commit_group;" ::: "memory")
#define CP_WAIT(n)  asm volatile("cp.async.wait_group %0;" :: "n"(n) : "memory")

__device__ __forceinline__ void ldmx4(uint32_t* r, uint32_t addr) {
    asm volatile("ldmatrix.sync.aligned.m8n8.x4.shared.b16 {%0,%1,%2,%3}, [%4];"
                 : "=r"(r[0]), "=r"(r[1]), "=r"(r[2]), "=r"(r[3]) : "r"(addr));
}
__device__ __forceinline__ void mma_f16(float* c, const uint32_t* a, const uint32_t* b) {
    asm volatile(
        "mma.sync.aligned.m16n8k16.row.col.f32.f16.f16.f32 "
        "{%0,%1,%2,%3}, {%4,%5,%6,%7}, {%8,%9}, {%0,%1,%2,%3};"
        : "+f"(c[0]), "+f"(c[1]), "+f"(c[2]), "+f"(c[3])
        : "r"(a[0]), "r"(a[1]), "r"(a[2]), "r"(a[3]), "r"(b[0]), "r"(b[1]));
}

// ---------------- single merged pre-pass ----------------
__global__ void prepass_kernel(const float* __restrict__ x,
                               const float* __restrict__ v) {
    if (blockIdx.x == 0 && threadIdx.x == 0) {
        int col = 0, step = 0, xx, yy, zz;
#define PUT(X, Y, Z) do { d_cell[col*3 + step] = (X) + 3*(Y) + 9*(Z); \
                          step = (step + 1) % 3; } while (0)
        for (xx = 0; xx < 3; xx++) {
            for (yy = 0; yy < 3; yy++) { for (zz = 0; zz < 3; zz++) PUT(xx,yy,zz); col++; }
            for (zz = 0; zz < 3; zz++) { for (yy = 0; yy < 3; yy++) PUT(xx,yy,zz); col++; }
            for (yy = 0; yy < 3; yy++) { zz = yy;     PUT(xx,yy,zz); } col++;
            for (yy = 0; yy < 3; yy++) { zz = 2 - yy; PUT(xx,yy,zz); } col++;
        }
        for (zz = 0; zz < 3; zz++) {
            for (yy = 0; yy < 3; yy++) { for (xx = 0; xx < 3; xx++) PUT(xx,yy,zz); col++; }
            for (yy = 0; yy < 3; yy++) { xx = yy;     PUT(xx,yy,zz); } col++;
            for (yy = 0; yy < 3; yy++) { xx = 2 - yy; PUT(xx,yy,zz); } col++;
        }
        for (yy = 0; yy < 3; yy++) {
            for (zz = 0; zz < 3; zz++) { xx = zz;     PUT(xx,yy,zz); } col++;
            for (zz = 0; zz < 3; zz++) { xx = 2 - zz; PUT(xx,yy,zz); } col++;
        }
        for (xx = 0; xx < 3; xx++) { yy = xx;     zz = xx;     PUT(xx,yy,zz); } col++;
        for (xx = 0; xx < 3; xx++) { yy = 2 - xx; zz = 2 - xx; PUT(xx,yy,zz); } col++;
        for (xx = 0; xx < 3; xx++) { yy = xx;     zz = 2 - xx; PUT(xx,yy,zz); } col++;
        for (xx = 0; xx < 3; xx++) { zz = xx;     yy = 2 - xx; PUT(xx,yy,zz); } col++;
#undef PUT
    }

    if (blockIdx.x < ROWS) {
        const int r = blockIdx.x;
        const float* vb = v + (size_t)r * CH;
        __half* dst = d_vTH + (size_t)r * CH * KTOT;
        for (int u = threadIdx.x; u < CH * (KTOT / 8); u += blockDim.x) {
            const int n  = u & (CH - 1);
            const int k8 = u >> 8;
            uint4 o;
            uint32_t h[4];
#pragma unroll
            for (int p = 0; p < 4; p++) {
                float lo = vb[(size_t)(k8 * 8 + 2 * p + 0) * OUTCOLS + n];
                float hi = vb[(size_t)(k8 * 8 + 2 * p + 1) * OUTCOLS + n];
                h[p] = h2_as_u32(__floats2half2_rn(lo, hi));
            }
            o.x = h[0]; o.y = h[1]; o.z = h[2]; o.w = h[3];
            *reinterpret_cast<uint4*>(dst + (size_t)n * KTOT + k8 * 8) = o;
        }
    }

    const size_t n8 = (size_t)BATCH * XCOLS / 8;
    const float4* src = reinterpret_cast<const float4*>(x);
    uint4* dst = reinterpret_cast<uint4*>(d_xH);
    for (size_t i = blockIdx.x * (size_t)blockDim.x + threadIdx.x;
         i < n8; i += (size_t)gridDim.x * blockDim.x) {
        float4 a = src[2 * i], b = src[2 * i + 1];
        uint4 o;
        o.x = h2_as_u32(__floats2half2_rn(a.x, a.y));
        o.y = h2_as_u32(__floats2half2_rn(a.z, a.w));
        o.z = h2_as_u32(__floats2half2_rn(b.x, b.y));
        o.w = h2_as_u32(__floats2half2_rn(b.z, b.w));
        dst[i] = o;
    }
}

// ---------------- main GEMM: batch-persistent fp16 mma.sync ----------------
// CTA (g, r): win-line r, full 256 columns, batch tiles {start_g .. start_g+n_g}.
// B (3 chunks) resident in smem; A double-buffered across batch tiles.
__global__ void __launch_bounds__(NTHREADS, 1)
tic_mma_kernel(const float* __restrict__ bias, float* __restrict__ out) {
    extern __shared__ char smem[];
    const uint32_t sb = smem_u32(smem);

    const int g = blockIdx.x;       // 0..5
    const int r = blockIdx.y;       // 0..48

    // batch-tile range: g<4 -> 11 tiles, g>=4 -> 10 tiles
    const int nbt   = (g < 4) ? 11 : 10;
    const int btsta = g * 10 + min(g, 4);

    const int tid = threadIdx.x;
    const int wid = tid >> 5, lid = tid & 31;
    const int wr = wid >> 2, wc = wid & 3;          // 4 x 4 warps; warp tile 32x64
    const int grp = lid >> 3, lr = lid & 7;

    const __half* vTb = d_vTH + (size_t)r * CH * KTOT;

    const int ld_row = tid >> 3;          // 0..63
    const int ld_f4  = tid & 7;

    // ldmatrix bases (bytes, rel. to chunk start)
    const uint32_t aBase = ((wr * 32 + ((grp & 1) << 3) + lr) * RSH + ((grp >> 1) << 3)) * 2;
    const uint32_t bBase = ((wc * 64 + ((grp & 1) << 3) + lr) * RSH + ((grp >> 1) << 3)) * 2;

    // ---- prologue: B (all 3 chunks) + A(bt0) into buf0, one commit group ----
#pragma unroll
    for (int c = 0; c < CHUNKS; c++) {
        const uint32_t sB = sb + OFF_B + c * B_CHUNK;
#pragma unroll
        for (int it = 0; it < 4; it++) {
            const int n = ld_row + it * 64;
            cp_async16(sB + n * ROWB + ld_f4 * 16,
                       vTb + (size_t)n * KTOT + c * KC + ld_f4 * 8);
        }
    }
    {
        const __half* xb = d_xH + (size_t)btsta * BM * XCOLS;
#pragma unroll
        for (int c = 0; c < CHUNKS; c++) {
            const uint32_t sA = sb + c * A_CHUNK;
            const int cellbase = d_cell[r * 3 + c] * IN_CH;
#pragma unroll
            for (int it = 0; it < 2; it++) {
                const int row = ld_row + it * 64;
                cp_async16(sA + row * ROWB + ld_f4 * 16,
                           xb + (size_t)row * XCOLS + cellbase + ld_f4 * 8);
            }
        }
    }
    CP_COMMIT();

    // bias registers (fixed per CTA)
    const int colbase = r * CH + wc * 64;
    float2 bv[8];
#pragma unroll
    for (int nt = 0; nt < 8; nt++)
        bv[nt] = *reinterpret_cast<const float2*>(bias + colbase + nt * 8 + 2 * (lid & 3));

    // ---- per-batch-tile loop ----
    for (int i = 0; i < nbt; i++) {
        const int bt = btsta + i;
        CP_WAIT(0);
        __syncthreads();     // A(bt) visible; all warps done with buf (i+1)&1

        // issue A(bt+1) into the other buffer (overlaps compute+epilogue)
        if (i + 1 < nbt) {
            const __half* xb = d_xH + (size_t)(bt + 1) * BM * XCOLS;
            const uint32_t bufn = ((i + 1) & 1) * A_BUF;
#pragma unroll
            for (int c = 0; c < CHUNKS; c++) {
                const uint32_t sA = sb + bufn + c * A_CHUNK;
                const int cellbase = d_cell[r * 3 + c] * IN_CH;
#pragma unroll
                for (int it = 0; it < 2; it++) {
                    const int row = ld_row + it * 64;
                    cp_async16(sA + row * ROWB + ld_f4 * 16,
                               xb + (size_t)row * XCOLS + cellbase + ld_f4 * 8);
                }
            }
            CP_COMMIT();
        }

        float acc[2][8][4];
#pragma unroll
        for (int a = 0; a < 2; a++)
#pragma unroll
            for (int b = 0; b < 8; b++)
#pragma unroll
                for (int q = 0; q < 4; q++) acc[a][b][q] = 0.0f;

        const uint32_t abuf = sb + (i & 1) * A_BUF;
#pragma unroll
        for (int c = 0; c < CHUNKS; c++) {
            const uint32_t sA = abuf + c * A_CHUNK;
            const uint32_t sB = sb + OFF_B + c * B_CHUNK;
#pragma unroll
            for (int ks = 0; ks < 4; ks++) {
                uint32_t af[2][4], bf[8][2];
#pragma unroll
                for (int mt = 0; mt < 2; mt++)
                    ldmx4(af[mt], sA + aBase + mt * 16 * ROWB + ks * 32);
#pragma unroll
                for (int np = 0; np < 4; np++) {
                    uint32_t t[4];
                    ldmx4(t, sB + bBase + np * 16 * ROWB + ks * 32);
                    bf[np * 2 + 0][0] = t[0]; bf[np * 2 + 0][1] = t[2];
                    bf[np * 2 + 1][0] = t[1]; bf[np * 2 + 1][1] = t[3];
                }
#pragma unroll
                for (int mt = 0; mt < 2; mt++)
#pragma unroll
                    for (int nt = 0; nt < 8; nt++)
                        mma_f16(acc[mt][nt], af[mt], bf[nt]);
            }
        }

        // epilogue for this batch tile
        const int row_lo = bt * BM + wr * 32 + (lid >> 2);
#pragma unroll
        for (int mt = 0; mt < 2; mt++) {
            float* o0 = out + (size_t)(row_lo + mt * 16) * OUTCOLS + colbase + 2 * (lid & 3);
            float* o1 = o0 + 8 * OUTCOLS;
#pragma unroll
            for (int nt = 0; nt < 8; nt++) {
                float2 v0 = { acc[mt][nt][0] + bv[nt].x, acc[mt][nt][1] + bv[nt].y };
                float2 v1 = { acc[mt][nt][2] + bv[nt].x, acc[mt][nt][3] + bv[nt].y };
                *reinterpret_cast<float2*>(o0 + nt * 8) = v0;
                *reinterpret_cast<float2*>(o1 + nt * 8) = v1;
            }
        }
    }
}

extern "C" void kernel_launch(void* const* d_in, const int* in_sizes, int n_in,
                              void* d_out, int out_size) {
    const float* x = nullptr;
    const float* v = nullptr;
    const float* b = nullptr;
    for (int i = 0; i < n_in; i++) {
        if (in_sizes[i] == BATCH * XCOLS)            x = (const float*)d_in[i];
        else if (in_sizes[i] == 3 * IN_CH * OUTCOLS) v = (const float*)d_in[i];
        else if (in_sizes[i] == OUTCOLS)             b = (const float*)d_in[i];
    }
    float* out = (float*)d_out;

    cudaFuncSetAttribute(tic_mma_kernel,
                         cudaFuncAttributeMaxDynamicSharedMemorySize, SMEM_TOTAL);

    prepass_kernel<<<2048, 256>>>(x, v);

    dim3 grid(NGRP, ROWS);   // (6, 49) = 294 CTAs, ~2 waves
    tic_mma_kernel<<<grid, NTHREADS, SMEM_TOTAL>>>(b, out);
}

// round 10
// speedup vs baseline: 4.6828x; 1.0295x over previous
#include <cuda_runtime.h>
#include <cuda_fp16.h>
#include <cstdint>
#include <cstring>

// ---------------- Problem constants ----------------
#define BATCH   8192
#define IN_CH   64
#define XCOLS   1728           // 27*64
#define OUTCOLS 12544          // 49*256
#define ROWS    49
#define CH      256
#define KTOT    192            // 3*64
#define CHUNKS  3
#define KC      64             // K (halves) per chunk == one board cell
#define BM      128
#define BN      256
#define NTHREADS 256
#define NGRP    6              // batch-tile groups (CTAs per win-line)

// SMEM: fp16 rows of 64 data halves padded to 72 (144B) -> conflict-free ldmatrix
#define RSH       72
#define ROWB      (RSH * 2)                    // 144 bytes per row
#define A_CHUNK   (BM * ROWB)                  // 18432
#define B_CHUNK   (BN * ROWB)                  // 36864
#define A_BUF     (CHUNKS * A_CHUNK)           // 55296
#define OFF_B     (2 * A_BUF)                  // 110592
#define SMEM_TOTAL (OFF_B + CHUNKS * B_CHUNK)  // 221184

__device__ int    d_cell[ROWS * 3];
__device__ __align__(16) __half d_xH[(size_t)BATCH * XCOLS];        // 28.3MB
__device__ __align__(16) __half d_vTH[(size_t)ROWS * CH * KTOT];    // 4.8MB, [r][perm(n)][k]

// ---------------- helpers ----------------
__device__ __forceinline__ uint32_t h2_as_u32(__half2 h) {
    uint32_t u;
    memcpy(&u, &h, 4);
    return u;
}
__device__ __forceinline__ uint32_t smem_u32(const void* p) {
    uint32_t a;
    asm("{ .reg .u64 t; cvta.to.shared.u64 t, %1; cvt.u32.u64 %0, t; }" : "=r"(a) : "l"(p));
    return a;
}
__device__ __forceinline__ void cp_async16(uint32_t dst, const void* src) {
    asm volatile("cp.async.cg.shared.global [%0], [%1], 16;"
                 :: "r"(dst), "l"(__cvta_generic_to_global(src)) : "memory");
}
#define CP_COMMIT() asm volatile("cp.async.commit_group;" ::: "memory")
#define CP_WAIT(n)  asm volatile("cp.async.wait_group %0;" :: "n"(n) : "memory")

__device__ __forceinline__ void ldmx4(uint32_t* r, uint32_t addr) {
    asm volatile("ldmatrix.sync.aligned.m8n8.x4.shared.b16 {%0,%1,%2,%3}, [%4];"
                 : "=r"(r[0]), "=r"(r[1]), "=r"(r[2]), "=r"(r[3]) : "r"(addr));
}
__device__ __forceinline__ void mma_f16(float* c, const uint32_t* a, const uint32_t* b) {
    asm volatile(
        "mma.sync.aligned.m16n8k16.row.col.f32.f16.f16.f32 "
        "{%0,%1,%2,%3}, {%4,%5,%6,%7}, {%8,%9}, {%0,%1,%2,%3};"
        : "+f"(c[0]), "+f"(c[1]), "+f"(c[2]), "+f"(c[3])
        : "r"(a[0]), "r"(a[1]), "r"(a[2]), "r"(a[3]), "r"(b[0]), "r"(b[1]));
}

// Column permutation: phys col n stored at MMA n-position perm(n) so that
// adjacent nt-fragment pairs hold 4 consecutive phys columns per lane quad.
__device__ __forceinline__ int permN(int n) {
    const int q = (n & 15) >> 2, h = (n >> 1) & 1, b = n & 1;
    return (n & ~15) | (h << 3) | (q << 1) | b;
}

// ---------------- single merged pre-pass ----------------
__global__ void prepass_kernel(const float* __restrict__ x,
                               const float* __restrict__ v) {
    if (blockIdx.x == 0 && threadIdx.x == 0) {
        int col = 0, step = 0, xx, yy, zz;
#define PUT(X, Y, Z) do { d_cell[col*3 + step] = (X) + 3*(Y) + 9*(Z); \
                          step = (step + 1) % 3; } while (0)
        for (xx = 0; xx < 3; xx++) {
            for (yy = 0; yy < 3; yy++) { for (zz = 0; zz < 3; zz++) PUT(xx,yy,zz); col++; }
            for (zz = 0; zz < 3; zz++) { for (yy = 0; yy < 3; yy++) PUT(xx,yy,zz); col++; }
            for (yy = 0; yy < 3; yy++) { zz = yy;     PUT(xx,yy,zz); } col++;
            for (yy = 0; yy < 3; yy++) { zz = 2 - yy; PUT(xx,yy,zz); } col++;
        }
        for (zz = 0; zz < 3; zz++) {
            for (yy = 0; yy < 3; yy++) { for (xx = 0; xx < 3; xx++) PUT(xx,yy,zz); col++; }
            for (yy = 0; yy < 3; yy++) { xx = yy;     PUT(xx,yy,zz); } col++;
            for (yy = 0; yy < 3; yy++) { xx = 2 - yy; PUT(xx,yy,zz); } col++;
        }
        for (yy = 0; yy < 3; yy++) {
            for (zz = 0; zz < 3; zz++) { xx = zz;     PUT(xx,yy,zz); } col++;
            for (zz = 0; zz < 3; zz++) { xx = 2 - zz; PUT(xx,yy,zz); } col++;
        }
        for (xx = 0; xx < 3; xx++) { yy = xx;     zz = xx;     PUT(xx,yy,zz); } col++;
        for (xx = 0; xx < 3; xx++) { yy = 2 - xx; zz = 2 - xx; PUT(xx,yy,zz); } col++;
        for (xx = 0; xx < 3; xx++) { yy = xx;     zz = 2 - xx; PUT(xx,yy,zz); } col++;
        for (xx = 0; xx < 3; xx++) { zz = xx;     yy = 2 - xx; PUT(xx,yy,zz); } col++;
#undef PUT
    }

    if (blockIdx.x < ROWS) {
        const int r = blockIdx.x;
        const float* vb = v + (size_t)r * CH;
        __half* dst = d_vTH + (size_t)r * CH * KTOT;
        for (int u = threadIdx.x; u < CH * (KTOT / 8); u += blockDim.x) {
            const int n  = u & (CH - 1);
            const int k8 = u >> 8;
            uint4 o;
            uint32_t h[4];
#pragma unroll
            for (int p = 0; p < 4; p++) {
                float lo = vb[(size_t)(k8 * 8 + 2 * p + 0) * OUTCOLS + n];
                float hi = vb[(size_t)(k8 * 8 + 2 * p + 1) * OUTCOLS + n];
                h[p] = h2_as_u32(__floats2half2_rn(lo, hi));
            }
            o.x = h[0]; o.y = h[1]; o.z = h[2]; o.w = h[3];
            *reinterpret_cast<uint4*>(dst + (size_t)permN(n) * KTOT + k8 * 8) = o;
        }
    }

    const size_t n8 = (size_t)BATCH * XCOLS / 8;
    const float4* src = reinterpret_cast<const float4*>(x);
    uint4* dst = reinterpret_cast<uint4*>(d_xH);
    for (size_t i = blockIdx.x * (size_t)blockDim.x + threadIdx.x;
         i < n8; i += (size_t)gridDim.x * blockDim.x) {
        float4 a = src[2 * i], b = src[2 * i + 1];
        uint4 o;
        o.x = h2_as_u32(__floats2half2_rn(a.x, a.y));
        o.y = h2_as_u32(__floats2half2_rn(a.z, a.w));
        o.z = h2_as_u32(__floats2half2_rn(b.x, b.y));
        o.w = h2_as_u32(__floats2half2_rn(b.z, b.w));
        dst[i] = o;
    }
}

// ---------------- main GEMM: 8 warps, 64x64 warp tile, frag ping-pong ----------------
__global__ void __launch_bounds__(NTHREADS, 1)
tic_mma_kernel(const float* __restrict__ bias, float* __restrict__ out) {
    extern __shared__ char smem[];
    const uint32_t sb = smem_u32(smem);

    const int g = blockIdx.x;       // 0..5
    const int r = blockIdx.y;       // 0..48

    const int nbt   = (g < 4) ? 11 : 10;
    const int btsta = g * 10 + min(g, 4);

    const int tid = threadIdx.x;
    const int wid = tid >> 5, lid = tid & 31;
    const int wr = wid >> 2, wc = wid & 3;          // 2 x 4 warps; warp tile 64x64
    const int grp = lid >> 3, lr = lid & 7;

    const __half* vTb = d_vTH + (size_t)r * CH * KTOT;

    const int ld_row = tid >> 3;          // 0..31
    const int ld_f4  = tid & 7;

    const uint32_t aBase = ((wr * 64 + ((grp & 1) << 3) + lr) * RSH + ((grp >> 1) << 3)) * 2;
    const uint32_t bBase = ((wc * 64 + ((grp & 1) << 3) + lr) * RSH + ((grp >> 1) << 3)) * 2;

    // ---- prologue: B (3 chunks) + A(bt0), one commit group ----
#pragma unroll
    for (int c = 0; c < CHUNKS; c++) {
        const uint32_t sB = sb + OFF_B + c * B_CHUNK;
#pragma unroll
        for (int it = 0; it < 8; it++) {
            const int n = ld_row + it * 32;
            cp_async16(sB + n * ROWB + ld_f4 * 16,
                       vTb + (size_t)n * KTOT + c * KC + ld_f4 * 8);
        }
    }
    {
        const __half* xb = d_xH + (size_t)btsta * BM * XCOLS;
#pragma unroll
        for (int c = 0; c < CHUNKS; c++) {
            const uint32_t sA = sb + c * A_CHUNK;
            const int cellbase = d_cell[r * 3 + c] * IN_CH;
#pragma unroll
            for (int it = 0; it < 4; it++) {
                const int row = ld_row + it * 32;
                cp_async16(sA + row * ROWB + ld_f4 * 16,
                           xb + (size_t)row * XCOLS + cellbase + ld_f4 * 8);
            }
        }
    }
    CP_COMMIT();

    const int colw = r * CH + wc * 64;

    // ---- per-batch-tile loop ----
    for (int i = 0; i < nbt; i++) {
        const int bt = btsta + i;
        CP_WAIT(0);
        __syncthreads();

        // issue A(bt+1) into the other buffer
        if (i + 1 < nbt) {
            const __half* xb = d_xH + (size_t)(bt + 1) * BM * XCOLS;
            const uint32_t bufn = ((i + 1) & 1) * A_BUF;
#pragma unroll
            for (int c = 0; c < CHUNKS; c++) {
                const uint32_t sA = sb + bufn + c * A_CHUNK;
                const int cellbase = d_cell[r * 3 + c] * IN_CH;
#pragma unroll
                for (int it = 0; it < 4; it++) {
                    const int row = ld_row + it * 32;
                    cp_async16(sA + row * ROWB + ld_f4 * 16,
                               xb + (size_t)row * XCOLS + cellbase + ld_f4 * 8);
                }
            }
            CP_COMMIT();
        }

        float acc[4][8][4];
#pragma unroll
        for (int a = 0; a < 4; a++)
#pragma unroll
            for (int b = 0; b < 8; b++)
#pragma unroll
                for (int q = 0; q < 4; q++) acc[a][b][q] = 0.0f;

        const uint32_t abuf = sb + (i & 1) * A_BUF;

        // fragment ping-pong over 12 flattened (chunk, ks) steps
        uint32_t af[2][4][4], bf[2][8][2];

#define LDFRAG(S, BUF) do {                                                    \
        const int c_ = (S) >> 2, ks_ = (S) & 3;                                \
        const uint32_t sA_ = abuf + c_ * A_CHUNK;                              \
        const uint32_t sB_ = sb + OFF_B + c_ * B_CHUNK;                        \
        _Pragma("unroll")                                                      \
        for (int mt = 0; mt < 4; mt++)                                         \
            ldmx4(af[BUF][mt], sA_ + aBase + mt * 16 * ROWB + ks_ * 32);       \
        _Pragma("unroll")                                                      \
        for (int np = 0; np < 4; np++) {                                       \
            uint32_t t[4];                                                     \
            ldmx4(t, sB_ + bBase + np * 16 * ROWB + ks_ * 32);                 \
            bf[BUF][np * 2 + 0][0] = t[0]; bf[BUF][np * 2 + 0][1] = t[2];      \
            bf[BUF][np * 2 + 1][0] = t[1]; bf[BUF][np * 2 + 1][1] = t[3];      \
        } } while (0)

        LDFRAG(0, 0);
#pragma unroll
        for (int s = 0; s < 12; s++) {
            if (s < 11) {
                if ((s + 1) & 1) LDFRAG(s + 1, 1);
                else             LDFRAG(s + 1, 0);
            }
            const int cur = s & 1;
#pragma unroll
            for (int mt = 0; mt < 4; mt++)
#pragma unroll
                for (int nt = 0; nt < 8; nt++)
                    mma_f16(acc[mt][nt], af[cur][mt], bf[cur][nt]);
        }
#undef LDFRAG

        // ---- epilogue: float4 stores (permuted B => consecutive phys cols) ----
        const int q4 = 4 * (lid & 3);
        const int row_lo = bt * BM + wr * 64 + (lid >> 2);
#pragma unroll
        for (int j = 0; j < 4; j++) {
            const float4 bj = *reinterpret_cast<const float4*>(bias + colw + 16 * j + q4);
#pragma unroll
            for (int mt = 0; mt < 4; mt++) {
                const float* e = acc[mt][2 * j + 0];
                const float* o = acc[mt][2 * j + 1];
                float* o0 = out + (size_t)(row_lo + mt * 16) * OUTCOLS + colw + 16 * j + q4;
                float* o1 = o0 + 8 * OUTCOLS;
                float4 v0 = { e[0] + bj.x, e[1] + bj.y, o[0] + bj.z, o[1] + bj.w };
                float4 v1 = { e[2] + bj.x, e[3] + bj.y, o[2] + bj.z, o[3] + bj.w };
                *reinterpret_cast<float4*>(o0) = v0;
                *reinterpret_cast<float4*>(o1) = v1;
            }
        }
    }
}

extern "C" void kernel_launch(void* const* d_in, const int* in_sizes, int n_in,
                              void* d_out, int out_size) {
    const float* x = nullptr;
    const float* v = nullptr;
    const float* b = nullptr;
    for (int i = 0; i < n_in; i++) {
        if (in_sizes[i] == BATCH * XCOLS)            x = (const float*)d_in[i];
        else if (in_sizes[i] == 3 * IN_CH * OUTCOLS) v = (const float*)d_in[i];
        else if (in_sizes[i] == OUTCOLS)             b = (const float*)d_in[i];
    }
    float* out = (float*)d_out;

    cudaFuncSetAttribute(tic_mma_kernel,
                         cudaFuncAttributeMaxDynamicSharedMemorySize, SMEM_TOTAL);

    prepass_kernel<<<2048, 256>>>(x, v);

    dim3 grid(NGRP, ROWS);   // (6, 49) = 294 CTAs, ~2 waves
    tic_mma_kernel<<<grid, NTHREADS, SMEM_TOTAL>>>(b, out);
}

// round 11
// speedup vs baseline: 5.3073x; 1.1333x over previous
#include <cuda_runtime.h>
#include <cuda_fp16.h>
#include <cstdint>
#include <cstring>

// ---------------- Problem constants ----------------
#define BATCH   8192
#define IN_CH   64
#define XCOLS   1728           // 27*64
#define OUTCOLS 12544          // 49*256
#define ROWS    49
#define CH      256
#define KTOT    192            // 3*64
#define CHUNKS  3
#define KC      64             // K (halves) per chunk == one board cell
#define BM      64
#define BN      256
#define NTHREADS 256
#define NGRP    6              // batch-tile groups (CTAs per win-line)
#define TILES_PER_LINE (BATCH / BM)   // 128

// SMEM: fp16 rows of 64 data halves padded to 72 (144B) -> conflict-free ldmatrix
#define RSH       72
#define ROWB      (RSH * 2)                    // 144 bytes per row
#define A_CHUNK   (BM * ROWB)                  // 9216
#define B_CHUNK   (BN * ROWB)                  // 36864
#define A_BUF     (CHUNKS * A_CHUNK)           // 27648
#define OFF_B     (2 * A_BUF)                  // 55296
#define SMEM_TOTAL (OFF_B + CHUNKS * B_CHUNK)  // 165888

__device__ int    d_cell[ROWS * 3];
__device__ __align__(16) __half d_xH[(size_t)BATCH * XCOLS];        // 28.3MB
__device__ __align__(16) __half d_vTH[(size_t)ROWS * CH * KTOT];    // 4.8MB, [r][perm(n)][k]

// ---------------- helpers ----------------
__device__ __forceinline__ uint32_t h2_as_u32(__half2 h) {
    uint32_t u;
    memcpy(&u, &h, 4);
    return u;
}
__device__ __forceinline__ uint32_t smem_u32(const void* p) {
    uint32_t a;
    asm("{ .reg .u64 t; cvta.to.shared.u64 t, %1; cvt.u32.u64 %0, t; }" : "=r"(a) : "l"(p));
    return a;
}
__device__ __forceinline__ void cp_async16(uint32_t dst, const void* src) {
    asm volatile("cp.async.cg.shared.global [%0], [%1], 16;"
                 :: "r"(dst), "l"(__cvta_generic_to_global(src)) : "memory");
}
#define CP_COMMIT() asm volatile("cp.async.commit_group;" ::: "memory")
#define CP_WAIT(n)  asm volatile("cp.async.wait_group %0;" :: "n"(n) : "memory")

__device__ __forceinline__ void ldmx4(uint32_t* r, uint32_t addr) {
    asm volatile("ldmatrix.sync.aligned.m8n8.x4.shared.b16 {%0,%1,%2,%3}, [%4];"
                 : "=r"(r[0]), "=r"(r[1]), "=r"(r[2]), "=r"(r[3]) : "r"(addr));
}
__device__ __forceinline__ void mma_f16(float* c, const uint32_t* a, const uint32_t* b) {
    asm volatile(
        "mma.sync.aligned.m16n8k16.row.col.f32.f16.f16.f32 "
        "{%0,%1,%2,%3}, {%4,%5,%6,%7}, {%8,%9}, {%0,%1,%2,%3};"
        : "+f"(c[0]), "+f"(c[1]), "+f"(c[2]), "+f"(c[3])
        : "r"(a[0]), "r"(a[1]), "r"(a[2]), "r"(a[3]), "r"(b[0]), "r"(b[1]));
}

// Column permutation: phys col n stored at MMA n-position perm(n) so that
// adjacent nt-fragment pairs hold 4 consecutive phys columns per lane quad.
__device__ __forceinline__ int permN(int n) {
    const int q = (n & 15) >> 2, h = (n >> 1) & 1, b = n & 1;
    return (n & ~15) | (h << 3) | (q << 1) | b;
}

// ---------------- single merged pre-pass ----------------
__global__ void prepass_kernel(const float* __restrict__ x,
                               const float* __restrict__ v) {
    if (blockIdx.x == 0 && threadIdx.x == 0) {
        int col = 0, step = 0, xx, yy, zz;
#define PUT(X, Y, Z) do { d_cell[col*3 + step] = (X) + 3*(Y) + 9*(Z); \
                          step = (step + 1) % 3; } while (0)
        for (xx = 0; xx < 3; xx++) {
            for (yy = 0; yy < 3; yy++) { for (zz = 0; zz < 3; zz++) PUT(xx,yy,zz); col++; }
            for (zz = 0; zz < 3; zz++) { for (yy = 0; yy < 3; yy++) PUT(xx,yy,zz); col++; }
            for (yy = 0; yy < 3; yy++) { zz = yy;     PUT(xx,yy,zz); } col++;
            for (yy = 0; yy < 3; yy++) { zz = 2 - yy; PUT(xx,yy,zz); } col++;
        }
        for (zz = 0; zz < 3; zz++) {
            for (yy = 0; yy < 3; yy++) { for (xx = 0; xx < 3; xx++) PUT(xx,yy,zz); col++; }
            for (yy = 0; yy < 3; yy++) { xx = yy;     PUT(xx,yy,zz); } col++;
            for (yy = 0; yy < 3; yy++) { xx = 2 - yy; PUT(xx,yy,zz); } col++;
        }
        for (yy = 0; yy < 3; yy++) {
            for (zz = 0; zz < 3; zz++) { xx = zz;     PUT(xx,yy,zz); } col++;
            for (zz = 0; zz < 3; zz++) { xx = 2 - zz; PUT(xx,yy,zz); } col++;
        }
        for (xx = 0; xx < 3; xx++) { yy = xx;     zz = xx;     PUT(xx,yy,zz); } col++;
        for (xx = 0; xx < 3; xx++) { yy = 2 - xx; zz = 2 - xx; PUT(xx,yy,zz); } col++;
        for (xx = 0; xx < 3; xx++) { yy = xx;     zz = 2 - xx; PUT(xx,yy,zz); } col++;
        for (xx = 0; xx < 3; xx++) { zz = xx;     yy = 2 - xx; PUT(xx,yy,zz); } col++;
#undef PUT
    }

    if (blockIdx.x < ROWS) {
        const int r = blockIdx.x;
        const float* vb = v + (size_t)r * CH;
        __half* dst = d_vTH + (size_t)r * CH * KTOT;
        for (int u = threadIdx.x; u < CH * (KTOT / 8); u += blockDim.x) {
            const int n  = u & (CH - 1);
            const int k8 = u >> 8;
            uint4 o;
            uint32_t h[4];
#pragma unroll
            for (int p = 0; p < 4; p++) {
                float lo = vb[(size_t)(k8 * 8 + 2 * p + 0) * OUTCOLS + n];
                float hi = vb[(size_t)(k8 * 8 + 2 * p + 1) * OUTCOLS + n];
                h[p] = h2_as_u32(__floats2half2_rn(lo, hi));
            }
            o.x = h[0]; o.y = h[1]; o.z = h[2]; o.w = h[3];
            *reinterpret_cast<uint4*>(dst + (size_t)permN(n) * KTOT + k8 * 8) = o;
        }
    }

    const size_t n8 = (size_t)BATCH * XCOLS / 8;
    const float4* src = reinterpret_cast<const float4*>(x);
    uint4* dst = reinterpret_cast<uint4*>(d_xH);
    for (size_t i = blockIdx.x * (size_t)blockDim.x + threadIdx.x;
         i < n8; i += (size_t)gridDim.x * blockDim.x) {
        float4 a = src[2 * i], b = src[2 * i + 1];
        uint4 o;
        o.x = h2_as_u32(__floats2half2_rn(a.x, a.y));
        o.y = h2_as_u32(__floats2half2_rn(a.z, a.w));
        o.z = h2_as_u32(__floats2half2_rn(b.x, b.y));
        o.w = h2_as_u32(__floats2half2_rn(b.z, b.w));
        dst[i] = o;
    }
}

// ---------------- main GEMM: epilogue folded into next tile's mainloop ----------------
__global__ void __launch_bounds__(NTHREADS, 1)
tic_mma_kernel(const float* __restrict__ bias, float* __restrict__ out) {
    extern __shared__ char smem[];
    const uint32_t sb = smem_u32(smem);

    const int g = blockIdx.x;       // 0..5
    const int r = blockIdx.y;       // 0..48

    // 128 tiles of 64 rows per line: g<2 -> 22 tiles, else 21
    const int nbt   = (g < 2) ? 22 : 21;
    const int btsta = g * 21 + min(g, 2);

    const int tid = threadIdx.x;
    const int wid = tid >> 5, lid = tid & 31;
    const int wr = wid >> 2, wc = wid & 3;          // 2 x 4 warps; warp tile 32x64
    const int grp = lid >> 3, lr = lid & 7;

    const __half* vTb = d_vTH + (size_t)r * CH * KTOT;

    const int ld_row = tid >> 3;          // 0..31
    const int ld_f4  = tid & 7;

    const uint32_t aBase = ((wr * 32 + ((grp & 1) << 3) + lr) * RSH + ((grp >> 1) << 3)) * 2;
    const uint32_t bBase = ((wc * 64 + ((grp & 1) << 3) + lr) * RSH + ((grp >> 1) << 3)) * 2;

    // ---- prologue: B (3 chunks) + A(bt0) into buf0, one commit group ----
#pragma unroll
    for (int c = 0; c < CHUNKS; c++) {
        const uint32_t sB = sb + OFF_B + c * B_CHUNK;
#pragma unroll
        for (int it = 0; it < 8; it++) {
            const int n = ld_row + it * 32;
            cp_async16(sB + n * ROWB + ld_f4 * 16,
                       vTb + (size_t)n * KTOT + c * KC + ld_f4 * 8);
        }
    }
    {
        const __half* xb = d_xH + (size_t)btsta * BM * XCOLS;
#pragma unroll
        for (int c = 0; c < CHUNKS; c++) {
            const uint32_t sA = sb + c * A_CHUNK;
            const int cellbase = d_cell[r * 3 + c] * IN_CH;
#pragma unroll
            for (int it = 0; it < 2; it++) {
                const int row = ld_row + it * 32;
                cp_async16(sA + row * ROWB + ld_f4 * 16,
                           xb + (size_t)row * XCOLS + cellbase + ld_f4 * 8);
            }
        }
    }
    CP_COMMIT();

    const int colw = r * CH + wc * 64;
    const int q4   = 4 * (lid & 3);
    const int rbase = wr * 32 + (lid >> 2);

    float4 bj[4];
#pragma unroll
    for (int j = 0; j < 4; j++)
        bj[j] = *reinterpret_cast<const float4*>(bias + colw + 16 * j + q4);

    float accA[2][8][4], accB[2][8][4];
    uint32_t af[2][2][4], bf[2][8][2];

#define LDFRAG(S, FB, ABUF) do {                                               \
        const int c_ = (S) >> 2, ks_ = (S) & 3;                                \
        const uint32_t sA_ = (ABUF) + c_ * A_CHUNK;                            \
        const uint32_t sB_ = sb + OFF_B + c_ * B_CHUNK;                        \
        _Pragma("unroll")                                                      \
        for (int mt = 0; mt < 2; mt++)                                         \
            ldmx4(af[FB][mt], sA_ + aBase + mt * 16 * ROWB + ks_ * 32);        \
        _Pragma("unroll")                                                      \
        for (int np = 0; np < 4; np++) {                                       \
            uint32_t t[4];                                                     \
            ldmx4(t, sB_ + bBase + np * 16 * ROWB + ks_ * 32);                 \
            bf[FB][np * 2 + 0][0] = t[0]; bf[FB][np * 2 + 0][1] = t[2];        \
            bf[FB][np * 2 + 1][0] = t[1]; bf[FB][np * 2 + 1][1] = t[3];        \
        } } while (0)

    // one bias-added float4 store of PRV tile, K in [0,16)
#define STORE_K(PRV, BTP, K) do {                                              \
        const int j_ = (K) >> 2, mt_ = ((K) >> 1) & 1, hf_ = (K) & 1;          \
        const float* e_ = PRV[mt_][2 * j_];                                    \
        const float* o_ = PRV[mt_][2 * j_ + 1];                                \
        float* p_ = out + (size_t)((BTP) * BM + rbase + mt_ * 16 + hf_ * 8)    \
                          * OUTCOLS + colw + 16 * j_ + q4;                     \
        float4 v_;                                                             \
        if ((hf_) == 0) { v_.x = e_[0] + bj[j_].x; v_.y = e_[1] + bj[j_].y;    \
                          v_.z = o_[0] + bj[j_].z; v_.w = o_[1] + bj[j_].w; }  \
        else            { v_.x = e_[2] + bj[j_].x; v_.y = e_[3] + bj[j_].y;    \
                          v_.z = o_[2] + bj[j_].z; v_.w = o_[3] + bj[j_].w; }  \
        *reinterpret_cast<float4*>(p_) = v_;                                   \
    } while (0)

    // one batch-tile iteration: compute CUR, store PRV interleaved
#define DO_ITER(CUR, PRV, I) do {                                              \
        const int bt_ = btsta + (I);                                           \
        CP_WAIT(0);                                                            \
        __syncthreads();                                                       \
        if ((I) + 1 < nbt) {                                                   \
            const __half* xb_ = d_xH + (size_t)(bt_ + 1) * BM * XCOLS;         \
            const uint32_t bufn_ = (((I) + 1) & 1) * A_BUF;                    \
            _Pragma("unroll")                                                  \
            for (int c = 0; c < CHUNKS; c++) {                                 \
                const uint32_t sA_ = sb + bufn_ + c * A_CHUNK;                 \
                const int cb_ = d_cell[r * 3 + c] * IN_CH;                     \
                _Pragma("unroll")                                              \
                for (int it = 0; it < 2; it++) {                               \
                    const int row_ = ld_row + it * 32;                         \
                    cp_async16(sA_ + row_ * ROWB + ld_f4 * 16,                 \
                               xb_ + (size_t)row_ * XCOLS + cb_ + ld_f4 * 8);  \
                }                                                              \
            }                                                                  \
            CP_COMMIT();                                                       \
        }                                                                      \
        _Pragma("unroll")                                                      \
        for (int a_ = 0; a_ < 2; a_++)                                         \
            _Pragma("unroll")                                                  \
            for (int b_ = 0; b_ < 8; b_++)                                     \
                _Pragma("unroll")                                              \
                for (int q_ = 0; q_ < 4; q_++) CUR[a_][b_][q_] = 0.0f;         \
        const uint32_t abuf_ = sb + ((I) & 1) * A_BUF;                         \
        LDFRAG(0, 0, abuf_);                                                   \
        _Pragma("unroll")                                                      \
        for (int s = 0; s < 12; s++) {                                         \
            if (s < 11) {                                                      \
                if ((s + 1) & 1) LDFRAG(s + 1, 1, abuf_);                      \
                else             LDFRAG(s + 1, 0, abuf_);                      \
            }                                                                  \
            const int cur_ = s & 1;                                            \
            _Pragma("unroll")                                                  \
            for (int mt = 0; mt < 2; mt++)                                     \
                _Pragma("unroll")                                              \
                for (int nt = 0; nt < 8; nt++)                                 \
                    mma_f16(CUR[mt][nt], af[cur_][mt], bf[cur_][nt]);          \
            if ((I) > 0 && s < 8) {                                            \
                STORE_K(PRV, bt_ - 1, 2 * s);                                  \
                STORE_K(PRV, bt_ - 1, 2 * s + 1);                              \
            }                                                                  \
        }                                                                      \
    } while (0)

    for (int i = 0; i < nbt; i++) {
        if (i & 1) DO_ITER(accB, accA, i);
        else       DO_ITER(accA, accB, i);
    }

    // drain final tile's stores
    {
        const int btl = btsta + nbt - 1;
        if ((nbt - 1) & 1) {
#pragma unroll
            for (int k = 0; k < 16; k++) STORE_K(accB, btl, k);
        } else {
#pragma unroll
            for (int k = 0; k < 16; k++) STORE_K(accA, btl, k);
        }
    }
#undef DO_ITER
#undef STORE_K
#undef LDFRAG
}

extern "C" void kernel_launch(void* const* d_in, const int* in_sizes, int n_in,
                              void* d_out, int out_size) {
    const float* x = nullptr;
    const float* v = nullptr;
    const float* b = nullptr;
    for (int i = 0; i < n_in; i++) {
        if (in_sizes[i] == BATCH * XCOLS)            x = (const float*)d_in[i];
        else if (in_sizes[i] == 3 * IN_CH * OUTCOLS) v = (const float*)d_in[i];
        else if (in_sizes[i] == OUTCOLS)             b = (const float*)d_in[i];
    }
    float* out = (float*)d_out;

    cudaFuncSetAttribute(tic_mma_kernel,
                         cudaFuncAttributeMaxDynamicSharedMemorySize, SMEM_TOTAL);

    prepass_kernel<<<2048, 256>>>(x, v);

    dim3 grid(NGRP, ROWS);   // (6, 49) = 294 CTAs, ~2 waves
    tic_mma_kernel<<<grid, NTHREADS, SMEM_TOTAL>>>(b, out);
}